// round 3
// baseline (speedup 1.0000x reference)
#include <cuda_runtime.h>
#include <cuda_bf16.h>

typedef unsigned long long ull;

#define F128 128
#define NRBF 20
#define ATS 132              // A^T stride for k_in/k_out tiles (128 rows + 4 pad)
#define HS  68               // hidden^T stride for edge tiles (64 edges + 4 pad)
#define MAX_ATOMS 50000
#define MAX_PAIRS 1600000

__device__ float g_h[(size_t)MAX_ATOMS * F128];
__device__ float g_agg[(size_t)MAX_ATOMS * F128];
__device__ int   g_cnt[MAX_ATOMS];
__device__ int   g_off[MAX_ATOMS];
__device__ float g_fperm[(size_t)MAX_PAIRS * NRBF];
__device__ float g_rcperm[MAX_PAIRS];
__device__ int   g_iperm[MAX_PAIRS];
__device__ int   g_jperm[MAX_PAIRS];

// ---------- f32x2 helpers ----------
__device__ __forceinline__ ull pk2(float x) {
    ull r; asm("mov.b64 %0, {%1, %1};" : "=l"(r) : "f"(x)); return r;
}
__device__ __forceinline__ ull fma2(ull a, ull b, ull c) {
    ull d; asm("fma.rn.f32x2 %0, %1, %2, %3;" : "=l"(d) : "l"(a), "l"(b), "l"(c)); return d;
}
__device__ __forceinline__ float2 upk(ull a) {
    float2 f; asm("mov.b64 {%0, %1}, %2;" : "=f"(f.x), "=f"(f.y) : "l"(a)); return f;
}
__device__ __forceinline__ void red4(float* p, float4 v) {
    asm volatile("red.global.add.v4.f32 [%0], {%1,%2,%3,%4};"
                 :: "l"(p), "f"(v.x), "f"(v.y), "f"(v.z), "f"(v.w) : "memory");
}
__device__ __forceinline__ float sspf(float x) {
    float e = __expf(-fabsf(x));
    return fmaxf(x, 0.0f) + __logf(1.0f + e) - 0.69314718056f;
}

// ---------- 4x8 register-tiled GEMM core (4 rows, 8 cols packed as 4 f32x2) ----------
__device__ __forceinline__ void init_acc4(const float* sbias, int n0, ull acc[4][4]) {
    const ulonglong2* bb = (const ulonglong2*)(sbias + n0);
    ulonglong2 b0 = bb[0], b1 = bb[1];
#pragma unroll
    for (int e = 0; e < 4; e++) {
        acc[e][0] = b0.x; acc[e][1] = b0.y; acc[e][2] = b1.x; acc[e][3] = b1.y;
    }
}

template <int AS>
__device__ __forceinline__ void gemm4(const float* __restrict__ sAT,
                                      const float* __restrict__ sB,
                                      int m0, int n0, ull acc[4][4]) {
#pragma unroll 8
    for (int k = 0; k < 128; k++) {
        const ulonglong2* wr = (const ulonglong2*)(sB + k * 128 + n0);
        ulonglong2 wA = wr[0], wB = wr[1];
        float4 ha = *(const float4*)(sAT + k * AS + m0);
        ull h0 = pk2(ha.x), h1 = pk2(ha.y), h2 = pk2(ha.z), h3 = pk2(ha.w);
        acc[0][0] = fma2(h0, wA.x, acc[0][0]);
        acc[0][1] = fma2(h0, wA.y, acc[0][1]);
        acc[0][2] = fma2(h0, wB.x, acc[0][2]);
        acc[0][3] = fma2(h0, wB.y, acc[0][3]);
        acc[1][0] = fma2(h1, wA.x, acc[1][0]);
        acc[1][1] = fma2(h1, wA.y, acc[1][1]);
        acc[1][2] = fma2(h1, wB.x, acc[1][2]);
        acc[1][3] = fma2(h1, wB.y, acc[1][3]);
        acc[2][0] = fma2(h2, wA.x, acc[2][0]);
        acc[2][1] = fma2(h2, wA.y, acc[2][1]);
        acc[2][2] = fma2(h2, wB.x, acc[2][2]);
        acc[2][3] = fma2(h2, wB.y, acc[2][3]);
        acc[3][0] = fma2(h3, wA.x, acc[3][0]);
        acc[3][1] = fma2(h3, wA.y, acc[3][1]);
        acc[3][2] = fma2(h3, wB.x, acc[3][2]);
        acc[3][3] = fma2(h3, wB.y, acc[3][3]);
    }
}

// ---------- zero agg + histogram counters ----------
__global__ void k_zero(int n4agg, int nAtoms) {
    int i = blockIdx.x * blockDim.x + threadIdx.x;
    if (i < n4agg) ((float4*)g_agg)[i] = make_float4(0.f, 0.f, 0.f, 0.f);
    if (i < nAtoms) g_cnt[i] = 0;
}

// ---------- histogram of idx_i ----------
__global__ void k_hist(const int* __restrict__ idx_i, int n) {
    int e = blockIdx.x * blockDim.x + threadIdx.x;
    if (e < n) atomicAdd(&g_cnt[idx_i[e]], 1);
}

// ---------- single-block exclusive scan over g_cnt -> g_off ----------
__global__ void k_scan(int n) {
    __shared__ int wsum[32];
    __shared__ int carry_s;
    int t = threadIdx.x;
    int lane = t & 31, wid = t >> 5;
    if (t == 0) carry_s = 0;
    __syncthreads();
    for (int base = 0; base < n; base += 1024) {
        int v = (base + t < n) ? g_cnt[base + t] : 0;
        int x = v;
#pragma unroll
        for (int off = 1; off < 32; off <<= 1) {
            int y = __shfl_up_sync(~0u, x, off);
            if (lane >= off) x += y;
        }
        if (lane == 31) wsum[wid] = x;
        __syncthreads();
        if (wid == 0) {
            int w = wsum[lane];
#pragma unroll
            for (int off = 1; off < 32; off <<= 1) {
                int y = __shfl_up_sync(~0u, w, off);
                if (lane >= off) w += y;
            }
            wsum[lane] = w;
        }
        __syncthreads();
        int warpoff = (wid > 0) ? wsum[wid - 1] : 0;
        int incl = x + warpoff;
        int carry = carry_s;
        int excl = incl - v + carry;
        if (base + t < n) g_off[base + t] = excl;
        __syncthreads();
        if (t == 1023) carry_s = carry + incl;
        __syncthreads();
    }
}

// ---------- scatter edges into idx_i-sorted order ----------
__global__ void k_scatter(const int* __restrict__ idx_i, const int* __restrict__ idx_j,
                          const float* __restrict__ rcut, const float* __restrict__ f,
                          int n) {
    int e = blockIdx.x * blockDim.x + threadIdx.x;
    if (e >= n) return;
    int i = idx_i[e];
    int pos = atomicAdd(&g_off[i], 1);
    g_iperm[pos] = i;
    g_jperm[pos] = idx_j[e];
    g_rcperm[pos] = rcut[e];
    const float4* src = (const float4*)(f + (size_t)e * NRBF);
    float4* dst = (float4*)(g_fperm + (size_t)pos * NRBF);
#pragma unroll
    for (int q = 0; q < 5; q++) dst[q] = src[q];
}

// ---------- kernel: h = x @ W_in + b_in  (512 threads, 128-row tiles) ----------
__global__ void __launch_bounds__(512) k_in(const float* __restrict__ x,
                                            const float* __restrict__ W,
                                            const float* __restrict__ b, int nRows) {
    extern __shared__ float sm[];
    float* sW = sm;              // 16384
    float* sb = sW + 16384;      // 128
    float* sAT = sb + 128;       // 128*ATS
    int t = threadIdx.x;
    for (int i = t; i < 4096; i += 512) ((float4*)sW)[i] = ((const float4*)W)[i];
    if (t < 128) sb[t] = b[t];
    int tx = t & 15, ty = t >> 4;  // ty in 0..31, 4 rows each
    int nTiles = (nRows + 127) >> 7;
    for (int tile = blockIdx.x; tile < nTiles; tile += gridDim.x) {
        int r0 = tile << 7;
        __syncthreads();
        for (int i = t; i < 4096; i += 512) {
            int row = i >> 5, kq = i & 31;
            float4 v = (r0 + row < nRows)
                           ? ((const float4*)(x + (size_t)(r0 + row) * 128))[kq]
                           : make_float4(0.f, 0.f, 0.f, 0.f);
            int kk = kq * 4;
            sAT[(kk + 0) * ATS + row] = v.x;
            sAT[(kk + 1) * ATS + row] = v.y;
            sAT[(kk + 2) * ATS + row] = v.z;
            sAT[(kk + 3) * ATS + row] = v.w;
        }
        __syncthreads();
        ull acc[4][4];
        init_acc4(sb, tx * 8, acc);
        gemm4<ATS>(sAT, sW, ty * 4, tx * 8, acc);
#pragma unroll
        for (int e = 0; e < 4; e++) {
            int row = r0 + ty * 4 + e;
            if (row < nRows) {
                float2 p0 = upk(acc[e][0]), p1 = upk(acc[e][1]);
                float2 p2 = upk(acc[e][2]), p3 = upk(acc[e][3]);
                float4* dst = (float4*)(g_h + (size_t)row * 128 + tx * 8);
                dst[0] = make_float4(p0.x, p0.y, p1.x, p1.y);
                dst[1] = make_float4(p2.x, p2.y, p3.x, p3.y);
            }
        }
    }
}

// ---------- fused edge pipeline (sorted edges, 64-edge tiles, 2 CTAs/SM) ----------
__global__ void __launch_bounds__(256, 2) k_edge(const float* __restrict__ Wf1,
                                                 const float* __restrict__ bf1,
                                                 const float* __restrict__ Wf2,
                                                 const float* __restrict__ bf2, int nPairs) {
    extern __shared__ float sm[];
    float* sWf2 = sm;                 // 16384
    float* sbf2 = sWf2 + 16384;       // 128
    float* sHid = sbf2 + 128;         // 128*HS = 8704
    float* sF = sHid + 128 * HS;      // 64*20 = 1280
    float* sRc = sF + 1280;           // 64
    int* sII = (int*)(sRc + 64);      // 64
    int* sJJ = sII + 64;              // 64

    int t = threadIdx.x;
    for (int i = t; i < 4096; i += 256) ((float4*)sWf2)[i] = ((const float4*)Wf2)[i];
    if (t < 128) sbf2[t] = bf2[t];

    int kx = t & 127, eh = t >> 7;
    float w1c[NRBF];
#pragma unroll
    for (int r = 0; r < NRBF; r++) w1c[r] = Wf1[r * 128 + kx];
    float b1 = bf1[kx];
    int tx = t & 15, ty = t >> 4;

    int nTiles = nPairs >> 6;
    for (int tile = blockIdx.x; tile < nTiles; tile += gridDim.x) {
        size_t e0g = (size_t)tile << 6;
        __syncthreads();
        for (int i = t; i < 320; i += 256)
            ((float4*)sF)[i] = ((const float4*)(g_fperm + e0g * NRBF))[i];
        if (t < 64) {
            sRc[t] = g_rcperm[e0g + t];
            sII[t] = g_iperm[e0g + t];
            sJJ[t] = g_jperm[e0g + t];
        }
        __syncthreads();
        // phase 1: hidden[e][kx] = ssp(bf1 + f[e]·Wf1[:,kx]) -> sHid[kx][e]
        {
            int ebase = eh * 32;
            for (int e4 = 0; e4 < 32; e4 += 4) {
                float hv[4];
#pragma unroll
                for (int c = 0; c < 4; c++) {
                    const float4* fp = (const float4*)(sF + (ebase + e4 + c) * NRBF);
                    float a = b1;
#pragma unroll
                    for (int q = 0; q < 5; q++) {
                        float4 fv = fp[q];
                        a = fmaf(w1c[4 * q + 0], fv.x, a);
                        a = fmaf(w1c[4 * q + 1], fv.y, a);
                        a = fmaf(w1c[4 * q + 2], fv.z, a);
                        a = fmaf(w1c[4 * q + 3], fv.w, a);
                    }
                    hv[c] = sspf(a);
                }
                *(float4*)(sHid + kx * HS + ebase + e4) =
                    make_float4(hv[0], hv[1], hv[2], hv[3]);
            }
        }
        __syncthreads();
        // phase 2: Wij tile GEMM
        ull acc[4][4];
        init_acc4(sbf2, tx * 8, acc);
        gemm4<HS>(sHid, sWf2, ty * 4, tx * 8, acc);
        // epilogue: scale, gather h[idx_j], run-accumulate by idx_i, flush RED
        int el0 = ty * 4;
        float4 A0 = make_float4(0.f, 0.f, 0.f, 0.f);
        float4 A1 = make_float4(0.f, 0.f, 0.f, 0.f);
        int cur = sII[el0];
#pragma unroll
        for (int e = 0; e < 4; e++) {
            int el = el0 + e;
            int ii = sII[el];
            if (ii != cur) {
                float* ap = g_agg + (size_t)cur * 128 + tx * 8;
                red4(ap, A0);
                red4(ap + 4, A1);
                A0 = make_float4(0.f, 0.f, 0.f, 0.f);
                A1 = make_float4(0.f, 0.f, 0.f, 0.f);
                cur = ii;
            }
            float rc = sRc[el];
            int jj = sJJ[el];
            float2 p0 = upk(acc[e][0]), p1 = upk(acc[e][1]);
            float2 p2 = upk(acc[e][2]), p3 = upk(acc[e][3]);
            const float4* hj = (const float4*)(g_h + (size_t)jj * 128 + tx * 8);
            float4 h0 = hj[0], h1 = hj[1];
            A0.x += p0.x * rc * h0.x; A0.y += p0.y * rc * h0.y;
            A0.z += p1.x * rc * h0.z; A0.w += p1.y * rc * h0.w;
            A1.x += p2.x * rc * h1.x; A1.y += p2.y * rc * h1.y;
            A1.z += p3.x * rc * h1.z; A1.w += p3.y * rc * h1.w;
        }
        float* ap = g_agg + (size_t)cur * 128 + tx * 8;
        red4(ap, A0);
        red4(ap + 4, A1);
    }
}

// ---------- kernel: out = ssp(agg@Wo1+bo1)@Wo2+bo2  (512 threads) ----------
__global__ void __launch_bounds__(512) k_out(const float* __restrict__ Wo1,
                                             const float* __restrict__ bo1,
                                             const float* __restrict__ Wo2,
                                             const float* __restrict__ bo2,
                                             float* __restrict__ out, int nRows) {
    extern __shared__ float sm[];
    float* sW1 = sm;
    float* sW2 = sW1 + 16384;
    float* sb1 = sW2 + 16384;
    float* sb2 = sb1 + 128;
    float* sBuf = sb2 + 128;  // 128*ATS
    int t = threadIdx.x;
    for (int i = t; i < 4096; i += 512) ((float4*)sW1)[i] = ((const float4*)Wo1)[i];
    for (int i = t; i < 4096; i += 512) ((float4*)sW2)[i] = ((const float4*)Wo2)[i];
    if (t < 128) { sb1[t] = bo1[t]; sb2[t] = bo2[t]; }
    int tx = t & 15, ty = t >> 4;  // ty 0..31, 4 rows each
    int nTiles = (nRows + 127) >> 7;
    for (int tile = blockIdx.x; tile < nTiles; tile += gridDim.x) {
        int r0 = tile << 7;
        __syncthreads();
        for (int i = t; i < 4096; i += 512) {
            int row = i >> 5, kq = i & 31;
            float4 v = (r0 + row < nRows)
                           ? ((const float4*)(g_agg + (size_t)(r0 + row) * 128))[kq]
                           : make_float4(0.f, 0.f, 0.f, 0.f);
            int kk = kq * 4;
            sBuf[(kk + 0) * ATS + row] = v.x;
            sBuf[(kk + 1) * ATS + row] = v.y;
            sBuf[(kk + 2) * ATS + row] = v.z;
            sBuf[(kk + 3) * ATS + row] = v.w;
        }
        __syncthreads();
        ull acc[4][4];
        init_acc4(sb1, tx * 8, acc);
        gemm4<ATS>(sBuf, sW1, ty * 4, tx * 8, acc);
        __syncthreads();
#pragma unroll
        for (int e = 0; e < 4; e++) {
            int row = ty * 4 + e;
            float2 p0 = upk(acc[e][0]), p1 = upk(acc[e][1]);
            float2 p2 = upk(acc[e][2]), p3 = upk(acc[e][3]);
            float vals[8] = {sspf(p0.x), sspf(p0.y), sspf(p1.x), sspf(p1.y),
                             sspf(p2.x), sspf(p2.y), sspf(p3.x), sspf(p3.y)};
            int f0 = tx * 8;
#pragma unroll
            for (int c = 0; c < 8; c++) sBuf[(f0 + c) * ATS + row] = vals[c];
        }
        __syncthreads();
        ull acc2[4][4];
        init_acc4(sb2, tx * 8, acc2);
        gemm4<ATS>(sBuf, sW2, ty * 4, tx * 8, acc2);
#pragma unroll
        for (int e = 0; e < 4; e++) {
            int row = r0 + ty * 4 + e;
            if (row < nRows) {
                float2 p0 = upk(acc2[e][0]), p1 = upk(acc2[e][1]);
                float2 p2 = upk(acc2[e][2]), p3 = upk(acc2[e][3]);
                float4* dst = (float4*)(out + (size_t)row * 128 + tx * 8);
                dst[0] = make_float4(p0.x, p0.y, p1.x, p1.y);
                dst[1] = make_float4(p2.x, p2.y, p3.x, p3.y);
            }
        }
    }
}

// ---------- launch ----------
extern "C" void kernel_launch(void* const* d_in, const int* in_sizes, int n_in,
                              void* d_out, int out_size) {
    const float* x    = (const float*)d_in[0];
    const float* f_ij = (const float*)d_in[1];
    const float* rcut = (const float*)d_in[2];
    const float* W_in = (const float*)d_in[3];
    const float* b_in = (const float*)d_in[4];
    const float* Wf1  = (const float*)d_in[5];
    const float* bf1  = (const float*)d_in[6];
    const float* Wf2  = (const float*)d_in[7];
    const float* bf2  = (const float*)d_in[8];
    const float* Wo1  = (const float*)d_in[9];
    const float* bo1  = (const float*)d_in[10];
    const float* Wo2  = (const float*)d_in[11];
    const float* bo2  = (const float*)d_in[12];
    const int* idx_i  = (const int*)d_in[13];
    const int* idx_j  = (const int*)d_in[14];
    float* out = (float*)d_out;

    int nAtoms = in_sizes[0] / 128;
    int nPairs = in_sizes[2];

    const int SMEM_IN   = (16384 + 128 + 128 * ATS) * 4;
    const int SMEM_EDGE = (16384 + 128 + 128 * HS + 1280 + 64 + 64 + 64) * 4;
    const int SMEM_OUT  = (16384 + 16384 + 128 + 128 + 128 * ATS) * 4;

    cudaFuncSetAttribute(k_in, cudaFuncAttributeMaxDynamicSharedMemorySize, SMEM_IN);
    cudaFuncSetAttribute(k_edge, cudaFuncAttributeMaxDynamicSharedMemorySize, SMEM_EDGE);
    cudaFuncSetAttribute(k_out, cudaFuncAttributeMaxDynamicSharedMemorySize, SMEM_OUT);

    int n4 = nAtoms * 32;
    k_zero<<<(n4 + 255) / 256, 256>>>(n4, nAtoms);
    k_hist<<<(nPairs + 255) / 256, 256>>>(idx_i, nPairs);
    k_scan<<<1, 1024>>>(nAtoms);
    k_scatter<<<(nPairs + 255) / 256, 256>>>(idx_i, idx_j, rcut, f_ij, nPairs);

    int rowTiles = (nAtoms + 127) / 128;
    k_in<<<rowTiles, 512, SMEM_IN>>>(x, W_in, b_in, nAtoms);
    k_edge<<<296, 256, SMEM_EDGE>>>(Wf1, bf1, Wf2, bf2, nPairs);
    k_out<<<rowTiles, 512, SMEM_OUT>>>(Wo1, bo1, Wo2, bo2, out, nAtoms);
}

// round 6
// speedup vs baseline: 1.5889x; 1.5889x over previous
#include <cuda_runtime.h>
#include <cuda_bf16.h>
#include <cstdint>

typedef unsigned long long ull;

#define F128 128
#define NRBF 20
#define ATS 132
#define MAX_ATOMS 50000

// fragment-ordered hidden buffer geometry (floats)
#define S_STRIDE 72          // per-kstep stride (pad for conflict-free writes)
#define NT_STRIDE (16 * S_STRIDE)  // 1152 floats per 8-edge ntile
#define SH_FLOATS (16 * NT_STRIDE) // 18432 floats

__device__ float g_h[(size_t)MAX_ATOMS * F128];
__device__ float g_agg[(size_t)MAX_ATOMS * F128];

// ---------- helpers ----------
__device__ __forceinline__ ull pk2(float x) { ull r; asm("mov.b64 %0, {%1, %1};" : "=l"(r) : "f"(x)); return r; }
__device__ __forceinline__ ull fma2(ull a, ull b, ull c) { ull d; asm("fma.rn.f32x2 %0, %1, %2, %3;" : "=l"(d) : "l"(a), "l"(b), "l"(c)); return d; }
__device__ __forceinline__ float2 upk(ull a) { float2 f; asm("mov.b64 {%0, %1}, %2;" : "=f"(f.x), "=f"(f.y) : "l"(a)); return f; }
__device__ __forceinline__ void red4(float* p, float4 v) {
    asm volatile("red.global.add.v4.f32 [%0], {%1,%2,%3,%4};" :: "l"(p), "f"(v.x), "f"(v.y), "f"(v.z), "f"(v.w) : "memory");
}
__device__ __forceinline__ float sspf(float x) {
    float e = __expf(-fabsf(x));
    return fmaxf(x, 0.0f) + __logf(1.0f + e) - 0.69314718056f;
}
__device__ __forceinline__ uint32_t tf32c(float f) {
    uint32_t u; asm("cvt.rna.tf32.f32 %0, %1;" : "=r"(u) : "f"(f)); return u;
}
__device__ __forceinline__ void mma_tf32(float d[4], const uint32_t a[4], uint32_t b0, uint32_t b1) {
    asm volatile(
        "mma.sync.aligned.m16n8k8.row.col.f32.tf32.tf32.f32 "
        "{%0,%1,%2,%3}, {%4,%5,%6,%7}, {%8,%9}, {%0,%1,%2,%3};"
        : "+f"(d[0]), "+f"(d[1]), "+f"(d[2]), "+f"(d[3])
        : "r"(a[0]), "r"(a[1]), "r"(a[2]), "r"(a[3]), "r"(b0), "r"(b1));
}

// ---------- SIMT 4x8 GEMM core (k_in / k_out) ----------
__device__ __forceinline__ void init_acc4(const float* sbias, int n0, ull acc[4][4]) {
    const ulonglong2* bb = (const ulonglong2*)(sbias + n0);
    ulonglong2 b0 = bb[0], b1 = bb[1];
#pragma unroll
    for (int e = 0; e < 4; e++) { acc[e][0] = b0.x; acc[e][1] = b0.y; acc[e][2] = b1.x; acc[e][3] = b1.y; }
}
template <int AS>
__device__ __forceinline__ void gemm4(const float* __restrict__ sAT, const float* __restrict__ sB,
                                      int m0, int n0, ull acc[4][4]) {
#pragma unroll 8
    for (int k = 0; k < 128; k++) {
        const ulonglong2* wr = (const ulonglong2*)(sB + k * 128 + n0);
        ulonglong2 wA = wr[0], wB = wr[1];
        float4 ha = *(const float4*)(sAT + k * AS + m0);
        ull h0 = pk2(ha.x), h1 = pk2(ha.y), h2 = pk2(ha.z), h3 = pk2(ha.w);
        acc[0][0] = fma2(h0, wA.x, acc[0][0]); acc[0][1] = fma2(h0, wA.y, acc[0][1]);
        acc[0][2] = fma2(h0, wB.x, acc[0][2]); acc[0][3] = fma2(h0, wB.y, acc[0][3]);
        acc[1][0] = fma2(h1, wA.x, acc[1][0]); acc[1][1] = fma2(h1, wA.y, acc[1][1]);
        acc[1][2] = fma2(h1, wB.x, acc[1][2]); acc[1][3] = fma2(h1, wB.y, acc[1][3]);
        acc[2][0] = fma2(h2, wA.x, acc[2][0]); acc[2][1] = fma2(h2, wA.y, acc[2][1]);
        acc[2][2] = fma2(h2, wB.x, acc[2][2]); acc[2][3] = fma2(h2, wB.y, acc[2][3]);
        acc[3][0] = fma2(h3, wA.x, acc[3][0]); acc[3][1] = fma2(h3, wA.y, acc[3][1]);
        acc[3][2] = fma2(h3, wB.x, acc[3][2]); acc[3][3] = fma2(h3, wB.y, acc[3][3]);
    }
}

// ---------- zero agg ----------
__global__ void k_zero(int n4) {
    int i = blockIdx.x * blockDim.x + threadIdx.x;
    if (i < n4) ((float4*)g_agg)[i] = make_float4(0.f, 0.f, 0.f, 0.f);
}

// ---------- h = x @ W_in + b_in ----------
__global__ void __launch_bounds__(512) k_in(const float* __restrict__ x,
                                            const float* __restrict__ W,
                                            const float* __restrict__ b, int nRows) {
    extern __shared__ float sm[];
    float* sW = sm;
    float* sb = sW + 16384;
    float* sAT = sb + 128;
    int t = threadIdx.x;
    for (int i = t; i < 4096; i += 512) ((float4*)sW)[i] = ((const float4*)W)[i];
    if (t < 128) sb[t] = b[t];
    int tx = t & 15, ty = t >> 4;
    int nTiles = (nRows + 127) >> 7;
    for (int tile = blockIdx.x; tile < nTiles; tile += gridDim.x) {
        int r0 = tile << 7;
        __syncthreads();
        for (int i = t; i < 4096; i += 512) {
            int row = i >> 5, kq = i & 31;
            float4 v = (r0 + row < nRows) ? ((const float4*)(x + (size_t)(r0 + row) * 128))[kq]
                                          : make_float4(0.f, 0.f, 0.f, 0.f);
            int kk = kq * 4;
            sAT[(kk + 0) * ATS + row] = v.x;
            sAT[(kk + 1) * ATS + row] = v.y;
            sAT[(kk + 2) * ATS + row] = v.z;
            sAT[(kk + 3) * ATS + row] = v.w;
        }
        __syncthreads();
        ull acc[4][4];
        init_acc4(sb, tx * 8, acc);
        gemm4<ATS>(sAT, sW, ty * 4, tx * 8, acc);
#pragma unroll
        for (int e = 0; e < 4; e++) {
            int row = r0 + ty * 4 + e;
            if (row < nRows) {
                float2 p0 = upk(acc[e][0]), p1 = upk(acc[e][1]);
                float2 p2 = upk(acc[e][2]), p3 = upk(acc[e][3]);
                float4* dst = (float4*)(g_h + (size_t)row * 128 + tx * 8);
                dst[0] = make_float4(p0.x, p0.y, p1.x, p1.y);
                dst[1] = make_float4(p2.x, p2.y, p3.x, p3.y);
            }
        }
    }
}

// ---------- fused edge pipeline: mma.sync tf32 ----------
// smem floats: sH[18432] | sF[2560] | sRc[128] | sBf2[128] | sII[128] | sJJ[128]
__global__ void __launch_bounds__(512, 1) k_edge(const float* __restrict__ f_ij,
                                                 const float* __restrict__ rcut,
                                                 const int* __restrict__ idx_i,
                                                 const int* __restrict__ idx_j,
                                                 const float* __restrict__ Wf1,
                                                 const float* __restrict__ bf1,
                                                 const float* __restrict__ Wf2,
                                                 const float* __restrict__ bf2, int nPairs) {
    extern __shared__ float sm[];
    float* sH = sm;                       // 18432 (also reused as sW: 128*132)
    float* sF = sH + SH_FLOATS;           // 2560
    float* sRc = sF + 2560;               // 128
    float* sBf2 = sRc + 128;              // 128
    int* sII = (int*)(sBf2 + 128);        // 128
    int* sJJ = sII + 128;                 // 128
    float* sW = sH;                       // alias

    int t = threadIdx.x;
    int w = t >> 5, lane = t & 31;

    if (t < 128) sBf2[t] = bf2[t];

    // phase-1 weights (per-thread hidden unit)
    int kx = t & 127;
    int egrp = t >> 7;  // 0..3 -> 32 edges each
    float w1c[NRBF];
#pragma unroll
    for (int r = 0; r < NRBF; r++) w1c[r] = Wf1[r * 128 + kx];
    float b1 = bf1[kx];
    int s1 = kx >> 3, laneK = kx & 3, halfK = (kx >> 2) & 1;
    float* wbase = sH + s1 * S_STRIDE + laneK * 2 + halfK;

    // A fragments: A[f][k] = Wf2[k*128+f], warp fg = w&7 owns filters fg*16..+15
    int fg = w & 7, ehalf = w >> 3;
    uint32_t af[16][4];
    {
        int fA = fg * 16 + (lane >> 2);
        int kA = lane & 3;
#pragma unroll
        for (int s = 0; s < 16; s++) {
            af[s][0] = tf32c(Wf2[(8 * s + kA) * 128 + fA]);
            af[s][1] = tf32c(Wf2[(8 * s + kA) * 128 + fA + 8]);
            af[s][2] = tf32c(Wf2[(8 * s + 4 + kA) * 128 + fA]);
            af[s][3] = tf32c(Wf2[(8 * s + 4 + kA) * 128 + fA + 8]);
        }
    }
    // B read pointer (float2 units): ntile stride 576, s stride 36
    const float2* bbase = (const float2*)sH + (size_t)ehalf * 8 * (NT_STRIDE / 2) + lane;

    int nTiles = nPairs >> 7;
    for (int tile = blockIdx.x; tile < nTiles; tile += gridDim.x) {
        size_t e0g = (size_t)tile << 7;
        __syncthreads();  // protect sF/sRc/sII/sJJ/sW from previous iteration
        for (int i = t; i < 640; i += 512)
            ((float4*)sF)[i] = ((const float4*)(f_ij + e0g * NRBF))[i];
        if (t < 128) {
            sRc[t] = rcut[e0g + t];
            sII[t] = idx_i[e0g + t];
            sJJ[t] = idx_j[e0g + t];
        }
        __syncthreads();
        // phase 1: hidden[e][kx] -> fragment-ordered sH
        {
            int ebase = egrp * 32;
#pragma unroll 4
            for (int i = 0; i < 32; i++) {
                int e = ebase + i;
                const float4* fp = (const float4*)(sF + e * NRBF);
                float a = b1;
#pragma unroll
                for (int q = 0; q < 5; q++) {
                    float4 fv = fp[q];
                    a = fmaf(w1c[4 * q + 0], fv.x, a);
                    a = fmaf(w1c[4 * q + 1], fv.y, a);
                    a = fmaf(w1c[4 * q + 2], fv.z, a);
                    a = fmaf(w1c[4 * q + 3], fv.w, a);
                }
                uint32_t hv = tf32c(sspf(a));
                wbase[(e >> 3) * NT_STRIDE + (e & 7) * 8] = __uint_as_float(hv);
            }
        }
        __syncthreads();
        // phase 2: warp GEMM — 8 ntiles x 16 ksteps of mma m16n8k8
        float acc[8][4];
#pragma unroll
        for (int nt = 0; nt < 8; nt++)
#pragma unroll
            for (int c = 0; c < 4; c++) acc[nt][c] = 0.0f;
#pragma unroll
        for (int nt = 0; nt < 8; nt++) {
            const float2* bp = bbase + nt * (NT_STRIDE / 2);
#pragma unroll
            for (int s = 0; s < 16; s++) {
                float2 b = bp[s * (S_STRIDE / 2)];
                mma_tf32(acc[nt], af[s], __float_as_uint(b.x), __float_as_uint(b.y));
            }
        }
        __syncthreads();  // all reads of sH done before overwrite as sW
        // writeback fragments -> sW[e][f] (stride 132)
        {
            int fA = fg * 16 + (lane >> 2);
#pragma unroll
            for (int nt = 0; nt < 8; nt++) {
                int eb = ehalf * 64 + nt * 8 + 2 * (lane & 3);
                sW[eb * 132 + fA]           = acc[nt][0];
                sW[(eb + 1) * 132 + fA]     = acc[nt][1];
                sW[eb * 132 + fA + 8]       = acc[nt][2];
                sW[(eb + 1) * 132 + fA + 8] = acc[nt][3];
            }
        }
        __syncthreads();
        // epilogue: (Wij + bf2) * rc * h[jj] -> red into agg[ii]
        {
            int el = t & 127, q = t >> 7;
            float rc = sRc[el];
            int jj = sJJ[el], ii = sII[el];
            const float4* hp = (const float4*)(g_h + (size_t)jj * 128) + q * 8;
            float* ap = g_agg + (size_t)ii * 128 + q * 32;
            const float* wrow = sW + el * 132 + q * 32;
            const float4* b2 = (const float4*)(sBf2 + q * 32);
#pragma unroll
            for (int i = 0; i < 8; i++) {
                float4 wv = *(const float4*)(wrow + 4 * i);
                float4 hv = hp[i];
                float4 bv = b2[i];
                float4 v = make_float4((wv.x + bv.x) * rc * hv.x,
                                       (wv.y + bv.y) * rc * hv.y,
                                       (wv.z + bv.z) * rc * hv.z,
                                       (wv.w + bv.w) * rc * hv.w);
                red4(ap + 4 * i, v);
            }
        }
    }
}

// ---------- out = ssp(agg@Wo1+bo1)@Wo2+bo2 ----------
__global__ void __launch_bounds__(512) k_out(const float* __restrict__ Wo1,
                                             const float* __restrict__ bo1,
                                             const float* __restrict__ Wo2,
                                             const float* __restrict__ bo2,
                                             float* __restrict__ out, int nRows) {
    extern __shared__ float sm[];
    float* sW1 = sm;
    float* sW2 = sW1 + 16384;
    float* sb1 = sW2 + 16384;
    float* sb2 = sb1 + 128;
    float* sBuf = sb2 + 128;
    int t = threadIdx.x;
    for (int i = t; i < 4096; i += 512) ((float4*)sW1)[i] = ((const float4*)Wo1)[i];
    for (int i = t; i < 4096; i += 512) ((float4*)sW2)[i] = ((const float4*)Wo2)[i];
    if (t < 128) { sb1[t] = bo1[t]; sb2[t] = bo2[t]; }
    int tx = t & 15, ty = t >> 4;
    int nTiles = (nRows + 127) >> 7;
    for (int tile = blockIdx.x; tile < nTiles; tile += gridDim.x) {
        int r0 = tile << 7;
        __syncthreads();
        for (int i = t; i < 4096; i += 512) {
            int row = i >> 5, kq = i & 31;
            float4 v = (r0 + row < nRows) ? ((const float4*)(g_agg + (size_t)(r0 + row) * 128))[kq]
                                          : make_float4(0.f, 0.f, 0.f, 0.f);
            int kk = kq * 4;
            sBuf[(kk + 0) * ATS + row] = v.x;
            sBuf[(kk + 1) * ATS + row] = v.y;
            sBuf[(kk + 2) * ATS + row] = v.z;
            sBuf[(kk + 3) * ATS + row] = v.w;
        }
        __syncthreads();
        ull acc[4][4];
        init_acc4(sb1, tx * 8, acc);
        gemm4<ATS>(sBuf, sW1, ty * 4, tx * 8, acc);
        __syncthreads();
#pragma unroll
        for (int e = 0; e < 4; e++) {
            int row = ty * 4 + e;
            float2 p0 = upk(acc[e][0]), p1 = upk(acc[e][1]);
            float2 p2 = upk(acc[e][2]), p3 = upk(acc[e][3]);
            float vals[8] = {sspf(p0.x), sspf(p0.y), sspf(p1.x), sspf(p1.y),
                             sspf(p2.x), sspf(p2.y), sspf(p3.x), sspf(p3.y)};
            int f0 = tx * 8;
#pragma unroll
            for (int c = 0; c < 8; c++) sBuf[(f0 + c) * ATS + row] = vals[c];
        }
        __syncthreads();
        ull acc2[4][4];
        init_acc4(sb2, tx * 8, acc2);
        gemm4<ATS>(sBuf, sW2, ty * 4, tx * 8, acc2);
#pragma unroll
        for (int e = 0; e < 4; e++) {
            int row = r0 + ty * 4 + e;
            if (row < nRows) {
                float2 p0 = upk(acc2[e][0]), p1 = upk(acc2[e][1]);
                float2 p2 = upk(acc2[e][2]), p3 = upk(acc2[e][3]);
                float4* dst = (float4*)(out + (size_t)row * 128 + tx * 8);
                dst[0] = make_float4(p0.x, p0.y, p1.x, p1.y);
                dst[1] = make_float4(p2.x, p2.y, p3.x, p3.y);
            }
        }
    }
}

// ---------- launch ----------
extern "C" void kernel_launch(void* const* d_in, const int* in_sizes, int n_in,
                              void* d_out, int out_size) {
    const float* x    = (const float*)d_in[0];
    const float* f_ij = (const float*)d_in[1];
    const float* rcut = (const float*)d_in[2];
    const float* W_in = (const float*)d_in[3];
    const float* b_in = (const float*)d_in[4];
    const float* Wf1  = (const float*)d_in[5];
    const float* bf1  = (const float*)d_in[6];
    const float* Wf2  = (const float*)d_in[7];
    const float* bf2  = (const float*)d_in[8];
    const float* Wo1  = (const float*)d_in[9];
    const float* bo1  = (const float*)d_in[10];
    const float* Wo2  = (const float*)d_in[11];
    const float* bo2  = (const float*)d_in[12];
    const int* idx_i  = (const int*)d_in[13];
    const int* idx_j  = (const int*)d_in[14];
    float* out = (float*)d_out;

    int nAtoms = in_sizes[0] / 128;
    int nPairs = in_sizes[2];

    const int SMEM_IN   = (16384 + 128 + 128 * ATS) * 4;
    const int SMEM_EDGE = (SH_FLOATS + 2560 + 128 + 128 + 128 + 128) * 4;
    const int SMEM_OUT  = (16384 + 16384 + 128 + 128 + 128 * ATS) * 4;

    cudaFuncSetAttribute(k_in, cudaFuncAttributeMaxDynamicSharedMemorySize, SMEM_IN);
    cudaFuncSetAttribute(k_edge, cudaFuncAttributeMaxDynamicSharedMemorySize, SMEM_EDGE);
    cudaFuncSetAttribute(k_out, cudaFuncAttributeMaxDynamicSharedMemorySize, SMEM_OUT);

    int n4 = nAtoms * 32;
    k_zero<<<(n4 + 255) / 256, 256>>>(n4);

    int rowTiles = (nAtoms + 127) / 128;
    k_in<<<rowTiles, 512, SMEM_IN>>>(x, W_in, b_in, nAtoms);
    k_edge<<<148, 512, SMEM_EDGE>>>(f_ij, rcut, idx_i, idx_j, Wf1, bf1, Wf2, bf2, nPairs);
    k_out<<<rowTiles, 512, SMEM_OUT>>>(Wo1, bo1, Wo2, bo2, out, nAtoms);
}

// round 8
// speedup vs baseline: 2.3907x; 1.5046x over previous
#include <cuda_runtime.h>
#include <cuda_bf16.h>
#include <cstdint>

typedef unsigned long long ull;

#define F128 128
#define NRBF 20
#define ATS 132
#define MAX_ATOMS 50000

// fragment-ordered hidden buffer (64-edge tile): [nt 0..7][s 0..15][72]
#define S_STRIDE 72
#define NT_STRIDE (16 * S_STRIDE)   // 1152
#define SH_FLOATS (8 * NT_STRIDE)   // 9216

__device__ float g_h[(size_t)MAX_ATOMS * F128];
__device__ float g_agg[(size_t)MAX_ATOMS * F128];

// ---------- helpers ----------
__device__ __forceinline__ ull pk2(float x) { ull r; asm("mov.b64 %0, {%1, %1};" : "=l"(r) : "f"(x)); return r; }
__device__ __forceinline__ ull fma2(ull a, ull b, ull c) { ull d; asm("fma.rn.f32x2 %0, %1, %2, %3;" : "=l"(d) : "l"(a), "l"(b), "l"(c)); return d; }
__device__ __forceinline__ float2 upk(ull a) { float2 f; asm("mov.b64 {%0, %1}, %2;" : "=f"(f.x), "=f"(f.y) : "l"(a)); return f; }
__device__ __forceinline__ void red4(float* p, float4 v) {
    asm volatile("red.global.add.v4.f32 [%0], {%1,%2,%3,%4};" :: "l"(p), "f"(v.x), "f"(v.y), "f"(v.z), "f"(v.w) : "memory");
}
__device__ __forceinline__ float sspf(float x) {
    float e = __expf(-fabsf(x));
    return fmaxf(x, 0.0f) + __logf(1.0f + e) - 0.69314718056f;
}
__device__ __forceinline__ uint32_t tf32c(float f) {
    uint32_t u; asm("cvt.rna.tf32.f32 %0, %1;" : "=r"(u) : "f"(f)); return u;
}
__device__ __forceinline__ void mma_tf32(float d[4], const uint32_t a[4], uint32_t b0, uint32_t b1) {
    asm volatile(
        "mma.sync.aligned.m16n8k8.row.col.f32.tf32.tf32.f32 "
        "{%0,%1,%2,%3}, {%4,%5,%6,%7}, {%8,%9}, {%0,%1,%2,%3};"
        : "+f"(d[0]), "+f"(d[1]), "+f"(d[2]), "+f"(d[3])
        : "r"(a[0]), "r"(a[1]), "r"(a[2]), "r"(a[3]), "r"(b0), "r"(b1));
}

// ---------- SIMT 8x8 GEMM core (k_in / k_out, 256 threads) ----------
__device__ __forceinline__ void init_acc8(const float* sbias, int n0, ull acc[8][4]) {
    const ulonglong2* bb = (const ulonglong2*)(sbias + n0);
    ulonglong2 b0 = bb[0], b1 = bb[1];
#pragma unroll
    for (int e = 0; e < 8; e++) { acc[e][0] = b0.x; acc[e][1] = b0.y; acc[e][2] = b1.x; acc[e][3] = b1.y; }
}
__device__ __forceinline__ void gemm8(const float* __restrict__ sAT, const float* __restrict__ sB,
                                      int m0, int n0, ull acc[8][4]) {
#pragma unroll 4
    for (int k = 0; k < 128; k++) {
        const ulonglong2* wr = (const ulonglong2*)(sB + k * 128 + n0);
        ulonglong2 wA = wr[0], wB = wr[1];
        const float4* hr = (const float4*)(sAT + k * ATS + m0);
        float4 ha = hr[0], hb = hr[1];
        ull h[8];
        h[0] = pk2(ha.x); h[1] = pk2(ha.y); h[2] = pk2(ha.z); h[3] = pk2(ha.w);
        h[4] = pk2(hb.x); h[5] = pk2(hb.y); h[6] = pk2(hb.z); h[7] = pk2(hb.w);
#pragma unroll
        for (int e = 0; e < 8; e++) {
            acc[e][0] = fma2(h[e], wA.x, acc[e][0]);
            acc[e][1] = fma2(h[e], wA.y, acc[e][1]);
            acc[e][2] = fma2(h[e], wB.x, acc[e][2]);
            acc[e][3] = fma2(h[e], wB.y, acc[e][3]);
        }
    }
}

// ---------- zero agg ----------
__global__ void k_zero(int n4) {
    int i = blockIdx.x * blockDim.x + threadIdx.x;
    if (i < n4) ((float4*)g_agg)[i] = make_float4(0.f, 0.f, 0.f, 0.f);
}

// ---------- h = x @ W_in + b_in (256 thr, 8x8) ----------
__global__ void __launch_bounds__(256) k_in(const float* __restrict__ x,
                                            const float* __restrict__ W,
                                            const float* __restrict__ b, int nRows) {
    extern __shared__ float sm[];
    float* sW = sm;
    float* sb = sW + 16384;
    float* sAT = sb + 128;
    int t = threadIdx.x;
    for (int i = t; i < 4096; i += 256) ((float4*)sW)[i] = ((const float4*)W)[i];
    if (t < 128) sb[t] = b[t];
    int tx = t & 15, ty = t >> 4;
    int nTiles = (nRows + 127) >> 7;
    for (int tile = blockIdx.x; tile < nTiles; tile += gridDim.x) {
        int r0 = tile << 7;
        __syncthreads();
        for (int i = t; i < 4096; i += 256) {
            int row = i >> 5, kq = i & 31;
            float4 v = (r0 + row < nRows) ? ((const float4*)(x + (size_t)(r0 + row) * 128))[kq]
                                          : make_float4(0.f, 0.f, 0.f, 0.f);
            int kk = kq * 4;
            sAT[(kk + 0) * ATS + row] = v.x;
            sAT[(kk + 1) * ATS + row] = v.y;
            sAT[(kk + 2) * ATS + row] = v.z;
            sAT[(kk + 3) * ATS + row] = v.w;
        }
        __syncthreads();
        ull acc[8][4];
        init_acc8(sb, tx * 8, acc);
        gemm8(sAT, sW, ty * 8, tx * 8, acc);
#pragma unroll
        for (int e = 0; e < 8; e++) {
            int row = r0 + ty * 8 + e;
            if (row < nRows) {
                float2 p0 = upk(acc[e][0]), p1 = upk(acc[e][1]);
                float2 p2 = upk(acc[e][2]), p3 = upk(acc[e][3]);
                float4* dst = (float4*)(g_h + (size_t)row * 128 + tx * 8);
                dst[0] = make_float4(p0.x, p0.y, p1.x, p1.y);
                dst[1] = make_float4(p2.x, p2.y, p3.x, p3.y);
            }
        }
    }
}

// ---------- fused edge pipeline: 64-edge tiles, 256 thr, 2 CTAs/SM ----------
__global__ void __launch_bounds__(256, 2) k_edge(const float* __restrict__ f_ij,
                                                 const float* __restrict__ rcut,
                                                 const int* __restrict__ idx_i,
                                                 const int* __restrict__ idx_j,
                                                 const float* __restrict__ Wf1,
                                                 const float* __restrict__ bf1,
                                                 const float* __restrict__ Wf2,
                                                 const float* __restrict__ bf2, int nPairs) {
    extern __shared__ float sm[];
    float* sH = sm;                       // 9216 (aliased as sW: 64*132 = 8448)
    float* sF = sH + SH_FLOATS;           // 1280
    float* sRc = sF + 1280;               // 64
    float* sBf2 = sRc + 64;               // 128
    int* sII = (int*)(sBf2 + 128);        // 64
    int* sJJ = sII + 64;                  // 64
    float* sW = sH;

    int t = threadIdx.x;
    int w = t >> 5, lane = t & 31;
    int lq = lane >> 2, lr = lane & 3;

    if (t < 128) sBf2[t] = bf2[t];

    // ----- persistent fragments -----
    // phase-2 A: warp w owns filters fA = w*16 + lq (+8)
    int fA = w * 16 + lq;
    uint32_t af[16][4];
#pragma unroll
    for (int s = 0; s < 16; s++) {
        af[s][0] = tf32c(Wf2[(8 * s + lr) * 128 + fA]);
        af[s][1] = tf32c(Wf2[(8 * s + lr) * 128 + fA + 8]);
        af[s][2] = tf32c(Wf2[(8 * s + 4 + lr) * 128 + fA]);
        af[s][3] = tf32c(Wf2[(8 * s + 4 + lr) * 128 + fA + 8]);
    }
    // phase-1 A: warp w owns hidden units fA (+8), K=20 padded to 24
    uint32_t af1[3][4];
#pragma unroll
    for (int s = 0; s < 3; s++) {
        int k0 = s * 8 + lr, k1 = s * 8 + 4 + lr;
        af1[s][0] = tf32c(Wf1[k0 * 128 + fA]);
        af1[s][1] = tf32c(Wf1[k0 * 128 + fA + 8]);
        af1[s][2] = (k1 < NRBF) ? tf32c(Wf1[k1 * 128 + fA]) : 0u;
        af1[s][3] = (k1 < NRBF) ? tf32c(Wf1[k1 * 128 + fA + 8]) : 0u;
    }
    float blo = bf1[fA], bhi = bf1[fA + 8];

    // phase-1 store bases (fragment-ordered sH), unit_lo = fA, unit_hi = fA+8
    int p1_lo = (fA >> 3) * S_STRIDE + (fA & 3) * 2 + ((fA >> 2) & 1);
    int p1_hi = p1_lo + S_STRIDE;
    // phase-2 B read pointer (float2 units)
    const float2* bbase = (const float2*)sH + lane;

    int nTiles = nPairs >> 6;
    for (int tile = blockIdx.x; tile < nTiles; tile += gridDim.x) {
        size_t e0g = (size_t)tile << 6;
        __syncthreads();  // prev tile fully done
        for (int i = t; i < 320; i += 256)
            ((float4*)sF)[i] = ((const float4*)(f_ij + e0g * NRBF))[i];
        if (t < 64) {
            sRc[t] = rcut[e0g + t];
            sII[t] = idx_i[e0g + t];
            sJJ[t] = idx_j[e0g + t];
        }
        __syncthreads();
        // ---- phase 1: hidden = ssp(f @ Wf1 + bf1) via mma, per ntile ----
#pragma unroll
        for (int nt = 0; nt < 8; nt++) {
            float a4[4] = {0.f, 0.f, 0.f, 0.f};
            const float* fe = sF + (nt * 8 + lq) * NRBF;
#pragma unroll
            for (int s = 0; s < 3; s++) {
                uint32_t b0 = tf32c(fe[s * 8 + lr]);
                uint32_t b1 = (s < 2) ? tf32c(fe[s * 8 + 4 + lr]) : 0u;
                mma_tf32(a4, af1[s], b0, b1);
            }
            int e0 = 2 * lr;  // LOCAL edge offset within ntile (bug fix vs R7)
            float* base = sH + nt * NT_STRIDE;
            base[p1_lo + e0 * 8]       = __uint_as_float(tf32c(sspf(a4[0] + blo)));
            base[p1_lo + (e0 + 1) * 8] = __uint_as_float(tf32c(sspf(a4[1] + blo)));
            base[p1_hi + e0 * 8]       = __uint_as_float(tf32c(sspf(a4[2] + bhi)));
            base[p1_hi + (e0 + 1) * 8] = __uint_as_float(tf32c(sspf(a4[3] + bhi)));
        }
        __syncthreads();
        // ---- phase 2: Wij = hidden @ Wf2 (warp: 16 filters x 64 edges) ----
        float acc[8][4];
#pragma unroll
        for (int nt = 0; nt < 8; nt++)
#pragma unroll
            for (int c = 0; c < 4; c++) acc[nt][c] = 0.0f;
#pragma unroll
        for (int nt = 0; nt < 8; nt++) {
            const float2* bp = bbase + nt * (NT_STRIDE / 2);
#pragma unroll
            for (int s = 0; s < 16; s++) {
                float2 b = bp[s * (S_STRIDE / 2)];
                mma_tf32(acc[nt], af[s], __float_as_uint(b.x), __float_as_uint(b.y));
            }
        }
        __syncthreads();  // all sH reads done
        // ---- writeback fragments -> sW[e][f] (stride 132) ----
#pragma unroll
        for (int nt = 0; nt < 8; nt++) {
            int eb = nt * 8 + 2 * lr;
            sW[eb * 132 + fA]           = acc[nt][0];
            sW[(eb + 1) * 132 + fA]     = acc[nt][1];
            sW[eb * 132 + fA + 8]       = acc[nt][2];
            sW[(eb + 1) * 132 + fA + 8] = acc[nt][3];
        }
        __syncthreads();
        // ---- epilogue: (Wij + bf2) * rc * h[jj] -> RED agg[ii] ----
        {
            int el = t & 63, q = t >> 6;
            float rc = sRc[el];
            int jj = sJJ[el], ii = sII[el];
            const float4* hp = (const float4*)(g_h + (size_t)jj * 128) + q * 8;
            float* ap = g_agg + (size_t)ii * 128 + q * 32;
            const float* wrow = sW + el * 132 + q * 32;
            const float4* b2 = (const float4*)(sBf2 + q * 32);
#pragma unroll
            for (int i = 0; i < 8; i++) {
                float4 wv = *(const float4*)(wrow + 4 * i);
                float4 hv = hp[i];
                float4 bv = b2[i];
                red4(ap + 4 * i, make_float4((wv.x + bv.x) * rc * hv.x,
                                             (wv.y + bv.y) * rc * hv.y,
                                             (wv.z + bv.z) * rc * hv.z,
                                             (wv.w + bv.w) * rc * hv.w));
            }
        }
    }
}

// ---------- out = ssp(agg@Wo1+bo1)@Wo2+bo2 (256 thr, 8x8) ----------
__global__ void __launch_bounds__(256) k_out(const float* __restrict__ Wo1,
                                             const float* __restrict__ bo1,
                                             const float* __restrict__ Wo2,
                                             const float* __restrict__ bo2,
                                             float* __restrict__ out, int nRows) {
    extern __shared__ float sm[];
    float* sW1 = sm;
    float* sW2 = sW1 + 16384;
    float* sb1 = sW2 + 16384;
    float* sb2 = sb1 + 128;
    float* sBuf = sb2 + 128;
    int t = threadIdx.x;
    for (int i = t; i < 4096; i += 256) ((float4*)sW1)[i] = ((const float4*)Wo1)[i];
    for (int i = t; i < 4096; i += 256) ((float4*)sW2)[i] = ((const float4*)Wo2)[i];
    if (t < 128) { sb1[t] = bo1[t]; sb2[t] = bo2[t]; }
    int tx = t & 15, ty = t >> 4;
    int nTiles = (nRows + 127) >> 7;
    for (int tile = blockIdx.x; tile < nTiles; tile += gridDim.x) {
        int r0 = tile << 7;
        __syncthreads();
        for (int i = t; i < 4096; i += 256) {
            int row = i >> 5, kq = i & 31;
            float4 v = (r0 + row < nRows) ? ((const float4*)(g_agg + (size_t)(r0 + row) * 128))[kq]
                                          : make_float4(0.f, 0.f, 0.f, 0.f);
            int kk = kq * 4;
            sBuf[(kk + 0) * ATS + row] = v.x;
            sBuf[(kk + 1) * ATS + row] = v.y;
            sBuf[(kk + 2) * ATS + row] = v.z;
            sBuf[(kk + 3) * ATS + row] = v.w;
        }
        __syncthreads();
        ull acc[8][4];
        init_acc8(sb1, tx * 8, acc);
        gemm8(sBuf, sW1, ty * 8, tx * 8, acc);
        __syncthreads();
#pragma unroll
        for (int e = 0; e < 8; e++) {
            int row = ty * 8 + e;
            float2 p0 = upk(acc[e][0]), p1 = upk(acc[e][1]);
            float2 p2 = upk(acc[e][2]), p3 = upk(acc[e][3]);
            float vals[8] = {sspf(p0.x), sspf(p0.y), sspf(p1.x), sspf(p1.y),
                             sspf(p2.x), sspf(p2.y), sspf(p3.x), sspf(p3.y)};
            int f0 = tx * 8;
#pragma unroll
            for (int c = 0; c < 8; c++) sBuf[(f0 + c) * ATS + row] = vals[c];
        }
        __syncthreads();
        ull acc2[8][4];
        init_acc8(sb2, tx * 8, acc2);
        gemm8(sBuf, sW2, ty * 8, tx * 8, acc2);
#pragma unroll
        for (int e = 0; e < 8; e++) {
            int row = r0 + ty * 8 + e;
            if (row < nRows) {
                float2 p0 = upk(acc2[e][0]), p1 = upk(acc2[e][1]);
                float2 p2 = upk(acc2[e][2]), p3 = upk(acc2[e][3]);
                float4* dst = (float4*)(out + (size_t)row * 128 + tx * 8);
                dst[0] = make_float4(p0.x, p0.y, p1.x, p1.y);
                dst[1] = make_float4(p2.x, p2.y, p3.x, p3.y);
            }
        }
    }
}

// ---------- launch ----------
extern "C" void kernel_launch(void* const* d_in, const int* in_sizes, int n_in,
                              void* d_out, int out_size) {
    const float* x    = (const float*)d_in[0];
    const float* f_ij = (const float*)d_in[1];
    const float* rcut = (const float*)d_in[2];
    const float* W_in = (const float*)d_in[3];
    const float* b_in = (const float*)d_in[4];
    const float* Wf1  = (const float*)d_in[5];
    const float* bf1  = (const float*)d_in[6];
    const float* Wf2  = (const float*)d_in[7];
    const float* bf2  = (const float*)d_in[8];
    const float* Wo1  = (const float*)d_in[9];
    const float* bo1  = (const float*)d_in[10];
    const float* Wo2  = (const float*)d_in[11];
    const float* bo2  = (const float*)d_in[12];
    const int* idx_i  = (const int*)d_in[13];
    const int* idx_j  = (const int*)d_in[14];
    float* out = (float*)d_out;

    int nAtoms = in_sizes[0] / 128;
    int nPairs = in_sizes[2];

    const int SMEM_IN   = (16384 + 128 + 128 * ATS) * 4;
    const int SMEM_EDGE = (SH_FLOATS + 1280 + 64 + 128 + 64 + 64) * 4;
    const int SMEM_OUT  = (16384 + 16384 + 128 + 128 + 128 * ATS) * 4;

    cudaFuncSetAttribute(k_in, cudaFuncAttributeMaxDynamicSharedMemorySize, SMEM_IN);
    cudaFuncSetAttribute(k_edge, cudaFuncAttributeMaxDynamicSharedMemorySize, SMEM_EDGE);
    cudaFuncSetAttribute(k_out, cudaFuncAttributeMaxDynamicSharedMemorySize, SMEM_OUT);

    int n4 = nAtoms * 32;
    k_zero<<<(n4 + 255) / 256, 256>>>(n4);

    int rowTiles = (nAtoms + 127) / 128;
    k_in<<<rowTiles, 256, SMEM_IN>>>(x, W_in, b_in, nAtoms);
    k_edge<<<296, 256, SMEM_EDGE>>>(f_ij, rcut, idx_i, idx_j, Wf1, bf1, Wf2, bf2, nPairs);
    k_out<<<rowTiles, 256, SMEM_OUT>>>(Wo1, bo1, Wo2, bo2, out, nAtoms);
}

// round 9
// speedup vs baseline: 2.7414x; 1.1467x over previous
#include <cuda_runtime.h>
#include <cuda_bf16.h>
#include <cstdint>

typedef unsigned long long ull;

#define F128 128
#define NRBF 20
#define MAX_ATOMS 50000

// fragment-ordered buffer geometry (shared by k_edge / k_in / k_out)
#define S_STRIDE 72
#define NT_STRIDE (16 * S_STRIDE)    // 1152
#define SH_FLOATS (8 * NT_STRIDE)    // k_edge: 8 ntiles (64 edges)
#define SH_OUT (16 * NT_STRIDE)      // k_in/k_out: 16 ntiles (128 atoms)

__device__ float g_h[(size_t)MAX_ATOMS * F128];
__device__ float g_agg[(size_t)MAX_ATOMS * F128];

// ---------- helpers ----------
__device__ __forceinline__ void red4(float* p, float4 v) {
    asm volatile("red.global.add.v4.f32 [%0], {%1,%2,%3,%4};" :: "l"(p), "f"(v.x), "f"(v.y), "f"(v.z), "f"(v.w) : "memory");
}
__device__ __forceinline__ float sspf(float x) {
    float e = __expf(-fabsf(x));
    return fmaxf(x, 0.0f) + __logf(1.0f + e) - 0.69314718056f;
}
__device__ __forceinline__ uint32_t tf32c(float f) {
    uint32_t u; asm("cvt.rna.tf32.f32 %0, %1;" : "=r"(u) : "f"(f)); return u;
}
__device__ __forceinline__ void mma_tf32(float d[4], const uint32_t a[4], uint32_t b0, uint32_t b1) {
    asm volatile(
        "mma.sync.aligned.m16n8k8.row.col.f32.tf32.tf32.f32 "
        "{%0,%1,%2,%3}, {%4,%5,%6,%7}, {%8,%9}, {%0,%1,%2,%3};"
        : "+f"(d[0]), "+f"(d[1]), "+f"(d[2]), "+f"(d[3])
        : "r"(a[0]), "r"(a[1]), "r"(a[2]), "r"(a[3]), "r"(b0), "r"(b1));
}

// ---------- k_in: h = x @ W_in + b_in, plus zero g_agg ----------
// 512 thr, 16 warps: fgrp = w&7 (filters fgrp*16..+15), ahalf = w>>3 (atoms 64*ahalf..+63)
__global__ void __launch_bounds__(512) k_in(const float* __restrict__ x,
                                            const float* __restrict__ W,
                                            const float* __restrict__ b, int nRows) {
    extern __shared__ float sm[];
    int t = threadIdx.x;
    int w = t >> 5, lane = t & 31;
    int lq = lane >> 2, lr = lane & 3;
    int fgrp = w & 7, ahalf = w >> 3;
    int fA = fgrp * 16 + lq;

    // zero g_agg (grid-stride)
    {
        size_t total4 = (size_t)nRows * 32;
        for (size_t i = (size_t)blockIdx.x * blockDim.x + t; i < total4;
             i += (size_t)gridDim.x * blockDim.x)
            ((float4*)g_agg)[i] = make_float4(0.f, 0.f, 0.f, 0.f);
    }

    // A fragments: A[f][k] = W[k*128+f]
    uint32_t af[16][4];
#pragma unroll
    for (int s = 0; s < 16; s++) {
        af[s][0] = tf32c(__ldg(W + (8 * s + lr) * 128 + fA));
        af[s][1] = tf32c(__ldg(W + (8 * s + lr) * 128 + fA + 8));
        af[s][2] = tf32c(__ldg(W + (8 * s + 4 + lr) * 128 + fA));
        af[s][3] = tf32c(__ldg(W + (8 * s + 4 + lr) * 128 + fA + 8));
    }
    float b_lo = __ldg(b + fA), b_hi = __ldg(b + fA + 8);

    int nTiles = (nRows + 127) >> 7;
    for (int tile = blockIdx.x; tile < nTiles; tile += gridDim.x) {
        int r0 = tile << 7;
        __syncthreads();
        // load x tile into fragment order (tf32-converted)
        for (int idx = t; idx < 4096; idx += 512) {
            int atom = idx >> 5, kq = idx & 31;
            int row = r0 + atom;
            float4 v = (row < nRows) ? ((const float4*)(x + (size_t)row * 128))[kq]
                                     : make_float4(0.f, 0.f, 0.f, 0.f);
            int base = (atom >> 3) * NT_STRIDE + (kq >> 1) * S_STRIDE + 8 * (atom & 7) + (kq & 1);
            sm[base + 0] = __uint_as_float(tf32c(v.x));
            sm[base + 2] = __uint_as_float(tf32c(v.y));
            sm[base + 4] = __uint_as_float(tf32c(v.z));
            sm[base + 6] = __uint_as_float(tf32c(v.w));
        }
        __syncthreads();
        float acc[8][4];
#pragma unroll
        for (int nt = 0; nt < 8; nt++) {
            acc[nt][0] = b_lo; acc[nt][1] = b_lo;
            acc[nt][2] = b_hi; acc[nt][3] = b_hi;
        }
        const float2* bbase = (const float2*)sm + lane;
#pragma unroll
        for (int nt = 0; nt < 8; nt++) {
            int gnt = ahalf * 8 + nt;
            const float2* bp = bbase + gnt * (NT_STRIDE / 2);
#pragma unroll
            for (int s = 0; s < 16; s++) {
                float2 bb = bp[s * (S_STRIDE / 2)];
                mma_tf32(acc[nt], af[s], __float_as_uint(bb.x), __float_as_uint(bb.y));
            }
        }
        // writeback scalar: rows gnt*8 + 2lr (+1), cols fA (+8)
#pragma unroll
        for (int nt = 0; nt < 8; nt++) {
            int gnt = ahalf * 8 + nt;
            int row0 = r0 + gnt * 8 + 2 * lr;
            if (row0 < nRows) {
                g_h[(size_t)row0 * 128 + fA] = acc[nt][0];
                g_h[(size_t)row0 * 128 + fA + 8] = acc[nt][2];
            }
            if (row0 + 1 < nRows) {
                g_h[(size_t)(row0 + 1) * 128 + fA] = acc[nt][1];
                g_h[(size_t)(row0 + 1) * 128 + fA + 8] = acc[nt][3];
            }
        }
    }
}

// ---------- fused edge pipeline (UNCHANGED from R8) ----------
__global__ void __launch_bounds__(256, 2) k_edge(const float* __restrict__ f_ij,
                                                 const float* __restrict__ rcut,
                                                 const int* __restrict__ idx_i,
                                                 const int* __restrict__ idx_j,
                                                 const float* __restrict__ Wf1,
                                                 const float* __restrict__ bf1,
                                                 const float* __restrict__ Wf2,
                                                 const float* __restrict__ bf2, int nPairs) {
    extern __shared__ float sm[];
    float* sH = sm;                       // 9216 (aliased as sW: 64*132)
    float* sF = sH + SH_FLOATS;           // 1280
    float* sRc = sF + 1280;               // 64
    float* sBf2 = sRc + 64;               // 128
    int* sII = (int*)(sBf2 + 128);        // 64
    int* sJJ = sII + 64;                  // 64
    float* sW = sH;

    int t = threadIdx.x;
    int w = t >> 5, lane = t & 31;
    int lq = lane >> 2, lr = lane & 3;

    if (t < 128) sBf2[t] = bf2[t];

    int fA = w * 16 + lq;
    uint32_t af[16][4];
#pragma unroll
    for (int s = 0; s < 16; s++) {
        af[s][0] = tf32c(Wf2[(8 * s + lr) * 128 + fA]);
        af[s][1] = tf32c(Wf2[(8 * s + lr) * 128 + fA + 8]);
        af[s][2] = tf32c(Wf2[(8 * s + 4 + lr) * 128 + fA]);
        af[s][3] = tf32c(Wf2[(8 * s + 4 + lr) * 128 + fA + 8]);
    }
    uint32_t af1[3][4];
#pragma unroll
    for (int s = 0; s < 3; s++) {
        int k0 = s * 8 + lr, k1 = s * 8 + 4 + lr;
        af1[s][0] = tf32c(Wf1[k0 * 128 + fA]);
        af1[s][1] = tf32c(Wf1[k0 * 128 + fA + 8]);
        af1[s][2] = (k1 < NRBF) ? tf32c(Wf1[k1 * 128 + fA]) : 0u;
        af1[s][3] = (k1 < NRBF) ? tf32c(Wf1[k1 * 128 + fA + 8]) : 0u;
    }
    float blo = bf1[fA], bhi = bf1[fA + 8];

    int p1_lo = (fA >> 3) * S_STRIDE + (fA & 3) * 2 + ((fA >> 2) & 1);
    int p1_hi = p1_lo + S_STRIDE;
    const float2* bbase = (const float2*)sH + lane;

    int nTiles = nPairs >> 6;
    for (int tile = blockIdx.x; tile < nTiles; tile += gridDim.x) {
        size_t e0g = (size_t)tile << 6;
        __syncthreads();
        for (int i = t; i < 320; i += 256)
            ((float4*)sF)[i] = ((const float4*)(f_ij + e0g * NRBF))[i];
        if (t < 64) {
            sRc[t] = rcut[e0g + t];
            sII[t] = idx_i[e0g + t];
            sJJ[t] = idx_j[e0g + t];
        }
        __syncthreads();
#pragma unroll
        for (int nt = 0; nt < 8; nt++) {
            float a4[4] = {0.f, 0.f, 0.f, 0.f};
            const float* fe = sF + (nt * 8 + lq) * NRBF;
#pragma unroll
            for (int s = 0; s < 3; s++) {
                uint32_t b0 = tf32c(fe[s * 8 + lr]);
                uint32_t b1 = (s < 2) ? tf32c(fe[s * 8 + 4 + lr]) : 0u;
                mma_tf32(a4, af1[s], b0, b1);
            }
            int e0 = 2 * lr;
            float* base = sH + nt * NT_STRIDE;
            base[p1_lo + e0 * 8]       = __uint_as_float(tf32c(sspf(a4[0] + blo)));
            base[p1_lo + (e0 + 1) * 8] = __uint_as_float(tf32c(sspf(a4[1] + blo)));
            base[p1_hi + e0 * 8]       = __uint_as_float(tf32c(sspf(a4[2] + bhi)));
            base[p1_hi + (e0 + 1) * 8] = __uint_as_float(tf32c(sspf(a4[3] + bhi)));
        }
        __syncthreads();
        float acc[8][4];
#pragma unroll
        for (int nt = 0; nt < 8; nt++)
#pragma unroll
            for (int c = 0; c < 4; c++) acc[nt][c] = 0.0f;
#pragma unroll
        for (int nt = 0; nt < 8; nt++) {
            const float2* bp = bbase + nt * (NT_STRIDE / 2);
#pragma unroll
            for (int s = 0; s < 16; s++) {
                float2 b = bp[s * (S_STRIDE / 2)];
                mma_tf32(acc[nt], af[s], __float_as_uint(b.x), __float_as_uint(b.y));
            }
        }
        __syncthreads();
#pragma unroll
        for (int nt = 0; nt < 8; nt++) {
            int eb = nt * 8 + 2 * lr;
            sW[eb * 132 + fA]           = acc[nt][0];
            sW[(eb + 1) * 132 + fA]     = acc[nt][1];
            sW[eb * 132 + fA + 8]       = acc[nt][2];
            sW[(eb + 1) * 132 + fA + 8] = acc[nt][3];
        }
        __syncthreads();
        {
            int el = t & 63, q = t >> 6;
            float rc = sRc[el];
            int jj = sJJ[el], ii = sII[el];
            const float4* hp = (const float4*)(g_h + (size_t)jj * 128) + q * 8;
            float* ap = g_agg + (size_t)ii * 128 + q * 32;
            const float* wrow = sW + el * 132 + q * 32;
            const float4* b2 = (const float4*)(sBf2 + q * 32);
#pragma unroll
            for (int i = 0; i < 8; i++) {
                float4 wv = *(const float4*)(wrow + 4 * i);
                float4 hv = hp[i];
                float4 bv = b2[i];
                red4(ap + 4 * i, make_float4((wv.x + bv.x) * rc * hv.x,
                                             (wv.y + bv.y) * rc * hv.y,
                                             (wv.z + bv.z) * rc * hv.z,
                                             (wv.w + bv.w) * rc * hv.w));
            }
        }
    }
}

// ---------- k_out: out = ssp(agg@Wo1+bo1)@Wo2+bo2 (mma tf32, 512 thr) ----------
__global__ void __launch_bounds__(512) k_out(const float* __restrict__ Wo1,
                                             const float* __restrict__ bo1,
                                             const float* __restrict__ Wo2,
                                             const float* __restrict__ bo2,
                                             float* __restrict__ out, int nRows) {
    extern __shared__ float sm[];
    int t = threadIdx.x;
    int w = t >> 5, lane = t & 31;
    int lq = lane >> 2, lr = lane & 3;
    int fgrp = w & 7, ahalf = w >> 3;
    int fA = fgrp * 16 + lq;

    // ssp-store positions (k = filter dimension)
    int p2_lo = (2 * fgrp) * S_STRIDE + 2 * (lq & 3) + (lq >> 2);
    int p2_hi = p2_lo + S_STRIDE;

    float bo1_lo = __ldg(bo1 + fA), bo1_hi = __ldg(bo1 + fA + 8);
    float bo2_lo = __ldg(bo2 + fA), bo2_hi = __ldg(bo2 + fA + 8);

    const float2* bbase = (const float2*)sm + lane;

    int nTiles = (nRows + 127) >> 7;
    for (int tile = blockIdx.x; tile < nTiles; tile += gridDim.x) {
        int r0 = tile << 7;
        __syncthreads();
        // load agg tile into fragment order
        for (int idx = t; idx < 4096; idx += 512) {
            int atom = idx >> 5, kq = idx & 31;
            int row = r0 + atom;
            float4 v = (row < nRows) ? ((const float4*)(g_agg + (size_t)row * 128))[kq]
                                     : make_float4(0.f, 0.f, 0.f, 0.f);
            int base = (atom >> 3) * NT_STRIDE + (kq >> 1) * S_STRIDE + 8 * (atom & 7) + (kq & 1);
            sm[base + 0] = __uint_as_float(tf32c(v.x));
            sm[base + 2] = __uint_as_float(tf32c(v.y));
            sm[base + 4] = __uint_as_float(tf32c(v.z));
            sm[base + 6] = __uint_as_float(tf32c(v.w));
        }
        // A fragments = Wo1^T
        uint32_t af[16][4];
#pragma unroll
        for (int s = 0; s < 16; s++) {
            af[s][0] = tf32c(__ldg(Wo1 + (8 * s + lr) * 128 + fA));
            af[s][1] = tf32c(__ldg(Wo1 + (8 * s + lr) * 128 + fA + 8));
            af[s][2] = tf32c(__ldg(Wo1 + (8 * s + 4 + lr) * 128 + fA));
            af[s][3] = tf32c(__ldg(Wo1 + (8 * s + 4 + lr) * 128 + fA + 8));
        }
        __syncthreads();
        // GEMM1: tmp^T[filter][atom]
        float acc[8][4];
#pragma unroll
        for (int nt = 0; nt < 8; nt++) {
            acc[nt][0] = bo1_lo; acc[nt][1] = bo1_lo;
            acc[nt][2] = bo1_hi; acc[nt][3] = bo1_hi;
        }
#pragma unroll
        for (int nt = 0; nt < 8; nt++) {
            int gnt = ahalf * 8 + nt;
            const float2* bp = bbase + gnt * (NT_STRIDE / 2);
#pragma unroll
            for (int s = 0; s < 16; s++) {
                float2 bb = bp[s * (S_STRIDE / 2)];
                mma_tf32(acc[nt], af[s], __float_as_uint(bb.x), __float_as_uint(bb.y));
            }
        }
        __syncthreads();  // all GEMM1 reads done
        // ssp + store back into fragment order (k = filter now)
#pragma unroll
        for (int nt = 0; nt < 8; nt++) {
            int gnt = ahalf * 8 + nt;
            float* base = sm + gnt * NT_STRIDE;
            int e0 = 2 * lr;
            base[p2_lo + e0 * 8]       = __uint_as_float(tf32c(sspf(acc[nt][0])));
            base[p2_lo + (e0 + 1) * 8] = __uint_as_float(tf32c(sspf(acc[nt][1])));
            base[p2_hi + e0 * 8]       = __uint_as_float(tf32c(sspf(acc[nt][2])));
            base[p2_hi + (e0 + 1) * 8] = __uint_as_float(tf32c(sspf(acc[nt][3])));
        }
        // A fragments = Wo2^T (reuse registers)
#pragma unroll
        for (int s = 0; s < 16; s++) {
            af[s][0] = tf32c(__ldg(Wo2 + (8 * s + lr) * 128 + fA));
            af[s][1] = tf32c(__ldg(Wo2 + (8 * s + lr) * 128 + fA + 8));
            af[s][2] = tf32c(__ldg(Wo2 + (8 * s + 4 + lr) * 128 + fA));
            af[s][3] = tf32c(__ldg(Wo2 + (8 * s + 4 + lr) * 128 + fA + 8));
        }
        __syncthreads();
        // GEMM2
#pragma unroll
        for (int nt = 0; nt < 8; nt++) {
            acc[nt][0] = bo2_lo; acc[nt][1] = bo2_lo;
            acc[nt][2] = bo2_hi; acc[nt][3] = bo2_hi;
        }
#pragma unroll
        for (int nt = 0; nt < 8; nt++) {
            int gnt = ahalf * 8 + nt;
            const float2* bp = bbase + gnt * (NT_STRIDE / 2);
#pragma unroll
            for (int s = 0; s < 16; s++) {
                float2 bb = bp[s * (S_STRIDE / 2)];
                mma_tf32(acc[nt], af[s], __float_as_uint(bb.x), __float_as_uint(bb.y));
            }
        }
        // writeback
#pragma unroll
        for (int nt = 0; nt < 8; nt++) {
            int gnt = ahalf * 8 + nt;
            int row0 = r0 + gnt * 8 + 2 * lr;
            if (row0 < nRows) {
                out[(size_t)row0 * 128 + fA] = acc[nt][0];
                out[(size_t)row0 * 128 + fA + 8] = acc[nt][2];
            }
            if (row0 + 1 < nRows) {
                out[(size_t)(row0 + 1) * 128 + fA] = acc[nt][1];
                out[(size_t)(row0 + 1) * 128 + fA + 8] = acc[nt][3];
            }
        }
    }
}

// ---------- launch ----------
extern "C" void kernel_launch(void* const* d_in, const int* in_sizes, int n_in,
                              void* d_out, int out_size) {
    const float* x    = (const float*)d_in[0];
    const float* f_ij = (const float*)d_in[1];
    const float* rcut = (const float*)d_in[2];
    const float* W_in = (const float*)d_in[3];
    const float* b_in = (const float*)d_in[4];
    const float* Wf1  = (const float*)d_in[5];
    const float* bf1  = (const float*)d_in[6];
    const float* Wf2  = (const float*)d_in[7];
    const float* bf2  = (const float*)d_in[8];
    const float* Wo1  = (const float*)d_in[9];
    const float* bo1  = (const float*)d_in[10];
    const float* Wo2  = (const float*)d_in[11];
    const float* bo2  = (const float*)d_in[12];
    const int* idx_i  = (const int*)d_in[13];
    const int* idx_j  = (const int*)d_in[14];
    float* out = (float*)d_out;

    int nAtoms = in_sizes[0] / 128;
    int nPairs = in_sizes[2];

    const int SMEM_INOUT = SH_OUT * 4;   // 73728
    const int SMEM_EDGE  = (SH_FLOATS + 1280 + 64 + 128 + 64 + 64) * 4;

    cudaFuncSetAttribute(k_in, cudaFuncAttributeMaxDynamicSharedMemorySize, SMEM_INOUT);
    cudaFuncSetAttribute(k_edge, cudaFuncAttributeMaxDynamicSharedMemorySize, SMEM_EDGE);
    cudaFuncSetAttribute(k_out, cudaFuncAttributeMaxDynamicSharedMemorySize, SMEM_INOUT);

    int rowTiles = (nAtoms + 127) / 128;
    k_in<<<rowTiles, 512, SMEM_INOUT>>>(x, W_in, b_in, nAtoms);
    k_edge<<<296, 256, SMEM_EDGE>>>(f_ij, rcut, idx_i, idx_j, Wf1, bf1, Wf2, bf2, nPairs);
    k_out<<<rowTiles, 512, SMEM_INOUT>>>(Wo1, bo1, Wo2, bo2, out, nAtoms);
}

// round 10
// speedup vs baseline: 2.7824x; 1.0150x over previous
#include <cuda_runtime.h>
#include <cuda_bf16.h>
#include <cuda_fp16.h>
#include <cstdint>

typedef unsigned long long ull;

#define F128 128
#define NRBF 20
#define MAX_ATOMS 50000

// k_in / k_out fragment-ordered geometry (tf32 path, unchanged from R9)
#define S_STRIDE 72
#define NT_STRIDE (16 * S_STRIDE)    // 1152
#define SH_OUT (16 * NT_STRIDE)      // 18432 floats

// k_edge smem word offsets (32-bit words)
#define EW_SW 0            // sW: 64*132 = 8448 words (fp32), aliases H2 (4608 words fp16x2)
#define EW_F2 8448         // sF2: 16*72 = 1152 words (fp16x2 pairs)
#define EW_RC 9600         // 64
#define EW_B2 9664         // 128
#define EW_II 9792         // 64
#define EW_JJ 9856         // 64
#define EW_TOTAL 9920

__device__ float g_h[(size_t)MAX_ATOMS * F128];
__device__ float g_agg[(size_t)MAX_ATOMS * F128];

// ---------- helpers ----------
__device__ __forceinline__ void red4(float* p, float4 v) {
    asm volatile("red.global.add.v4.f32 [%0], {%1,%2,%3,%4};" :: "l"(p), "f"(v.x), "f"(v.y), "f"(v.z), "f"(v.w) : "memory");
}
__device__ __forceinline__ float sspf(float x) {
    float e = __expf(-fabsf(x));
    return fmaxf(x, 0.0f) + __logf(1.0f + e) - 0.69314718056f;
}
__device__ __forceinline__ uint32_t tf32c(float f) {
    uint32_t u; asm("cvt.rna.tf32.f32 %0, %1;" : "=r"(u) : "f"(f)); return u;
}
__device__ __forceinline__ uint32_t packh2(float lo, float hi) {
    __half2 h = __floats2half2_rn(lo, hi);   // .x = lo
    return *reinterpret_cast<uint32_t*>(&h);
}
__device__ __forceinline__ void mma_tf32(float d[4], const uint32_t a[4], uint32_t b0, uint32_t b1) {
    asm volatile(
        "mma.sync.aligned.m16n8k8.row.col.f32.tf32.tf32.f32 "
        "{%0,%1,%2,%3}, {%4,%5,%6,%7}, {%8,%9}, {%0,%1,%2,%3};"
        : "+f"(d[0]), "+f"(d[1]), "+f"(d[2]), "+f"(d[3])
        : "r"(a[0]), "r"(a[1]), "r"(a[2]), "r"(a[3]), "r"(b0), "r"(b1));
}
__device__ __forceinline__ void mma_f16(float d[4], const uint32_t a[4], uint32_t b0, uint32_t b1) {
    asm volatile(
        "mma.sync.aligned.m16n8k16.row.col.f32.f16.f16.f32 "
        "{%0,%1,%2,%3}, {%4,%5,%6,%7}, {%8,%9}, {%0,%1,%2,%3};"
        : "+f"(d[0]), "+f"(d[1]), "+f"(d[2]), "+f"(d[3])
        : "r"(a[0]), "r"(a[1]), "r"(a[2]), "r"(a[3]), "r"(b0), "r"(b1));
}

// ---------- k_in: h = x @ W_in + b_in, plus zero g_agg (unchanged from R9) ----------
__global__ void __launch_bounds__(512) k_in(const float* __restrict__ x,
                                            const float* __restrict__ W,
                                            const float* __restrict__ b, int nRows) {
    extern __shared__ float sm[];
    int t = threadIdx.x;
    int w = t >> 5, lane = t & 31;
    int lq = lane >> 2, lr = lane & 3;
    int fgrp = w & 7, ahalf = w >> 3;
    int fA = fgrp * 16 + lq;

    {
        size_t total4 = (size_t)nRows * 32;
        for (size_t i = (size_t)blockIdx.x * blockDim.x + t; i < total4;
             i += (size_t)gridDim.x * blockDim.x)
            ((float4*)g_agg)[i] = make_float4(0.f, 0.f, 0.f, 0.f);
    }

    uint32_t af[16][4];
#pragma unroll
    for (int s = 0; s < 16; s++) {
        af[s][0] = tf32c(__ldg(W + (8 * s + lr) * 128 + fA));
        af[s][1] = tf32c(__ldg(W + (8 * s + lr) * 128 + fA + 8));
        af[s][2] = tf32c(__ldg(W + (8 * s + 4 + lr) * 128 + fA));
        af[s][3] = tf32c(__ldg(W + (8 * s + 4 + lr) * 128 + fA + 8));
    }
    float b_lo = __ldg(b + fA), b_hi = __ldg(b + fA + 8);

    int nTiles = (nRows + 127) >> 7;
    for (int tile = blockIdx.x; tile < nTiles; tile += gridDim.x) {
        int r0 = tile << 7;
        __syncthreads();
        for (int idx = t; idx < 4096; idx += 512) {
            int atom = idx >> 5, kq = idx & 31;
            int row = r0 + atom;
            float4 v = (row < nRows) ? ((const float4*)(x + (size_t)row * 128))[kq]
                                     : make_float4(0.f, 0.f, 0.f, 0.f);
            int base = (atom >> 3) * NT_STRIDE + (kq >> 1) * S_STRIDE + 8 * (atom & 7) + (kq & 1);
            sm[base + 0] = __uint_as_float(tf32c(v.x));
            sm[base + 2] = __uint_as_float(tf32c(v.y));
            sm[base + 4] = __uint_as_float(tf32c(v.z));
            sm[base + 6] = __uint_as_float(tf32c(v.w));
        }
        __syncthreads();
        float acc[8][4];
#pragma unroll
        for (int nt = 0; nt < 8; nt++) {
            acc[nt][0] = b_lo; acc[nt][1] = b_lo;
            acc[nt][2] = b_hi; acc[nt][3] = b_hi;
        }
        const float2* bbase = (const float2*)sm + lane;
#pragma unroll
        for (int nt = 0; nt < 8; nt++) {
            int gnt = ahalf * 8 + nt;
            const float2* bp = bbase + gnt * (NT_STRIDE / 2);
#pragma unroll
            for (int s = 0; s < 16; s++) {
                float2 bb = bp[s * (S_STRIDE / 2)];
                mma_tf32(acc[nt], af[s], __float_as_uint(bb.x), __float_as_uint(bb.y));
            }
        }
#pragma unroll
        for (int nt = 0; nt < 8; nt++) {
            int gnt = ahalf * 8 + nt;
            int row0 = r0 + gnt * 8 + 2 * lr;
            if (row0 < nRows) {
                g_h[(size_t)row0 * 128 + fA] = acc[nt][0];
                g_h[(size_t)row0 * 128 + fA + 8] = acc[nt][2];
            }
            if (row0 + 1 < nRows) {
                g_h[(size_t)(row0 + 1) * 128 + fA] = acc[nt][1];
                g_h[(size_t)(row0 + 1) * 128 + fA + 8] = acc[nt][3];
            }
        }
    }
}

// ---------- fused edge pipeline: fp16 m16n8k16 mma ----------
__global__ void __launch_bounds__(256, 2) k_edge(const float* __restrict__ f_ij,
                                                 const float* __restrict__ rcut,
                                                 const int* __restrict__ idx_i,
                                                 const int* __restrict__ idx_j,
                                                 const float* __restrict__ Wf1,
                                                 const float* __restrict__ bf1,
                                                 const float* __restrict__ Wf2,
                                                 const float* __restrict__ bf2, int nPairs) {
    extern __shared__ float sm[];
    float* sW = sm + EW_SW;                 // fp32 64x132, aliases H2
    uint32_t* H2w = (uint32_t*)(sm + EW_SW);  // fp16x2 words: [k2][n], stride 72
    __half* Hh = (__half*)(sm + EW_SW);
    uint32_t* sF2 = (uint32_t*)(sm + EW_F2);  // fp16x2 [kp][e], stride 72
    float* sRc = sm + EW_RC;
    float* sBf2 = sm + EW_B2;
    int* sII = (int*)(sm + EW_II);
    int* sJJ = (int*)(sm + EW_JJ);

    int t = threadIdx.x;
    int w = t >> 5, lane = t & 31;
    int lq = lane >> 2, lr = lane & 3;

    if (t < 128) sBf2[t] = bf2[t];
    // zero sF2 pads (kp 10..15) once
    for (int i = t; i < 432; i += 256) sF2[720 + i] = 0;

    int fA = w * 16 + lq;
    // phase-2 A fragments: A[f][k] = Wf2[k*128+f], fp16 pairs, 8 chunks of k16
    uint32_t af[8][4];
#pragma unroll
    for (int s = 0; s < 8; s++) {
        int k0 = 16 * s + 2 * lr, k1 = 16 * s + 8 + 2 * lr;
        af[s][0] = packh2(Wf2[k0 * 128 + fA],     Wf2[(k0 + 1) * 128 + fA]);
        af[s][1] = packh2(Wf2[k0 * 128 + fA + 8], Wf2[(k0 + 1) * 128 + fA + 8]);
        af[s][2] = packh2(Wf2[k1 * 128 + fA],     Wf2[(k1 + 1) * 128 + fA]);
        af[s][3] = packh2(Wf2[k1 * 128 + fA + 8], Wf2[(k1 + 1) * 128 + fA + 8]);
    }
    // phase-1 A fragments: A[hidden fA][k=rbf], K=20 padded to 32 (2 chunks of 16)
    uint32_t af1[2][4];
    {
        int k0 = 2 * lr, k1 = 8 + 2 * lr;
        af1[0][0] = packh2(Wf1[k0 * 128 + fA],     Wf1[(k0 + 1) * 128 + fA]);
        af1[0][1] = packh2(Wf1[k0 * 128 + fA + 8], Wf1[(k0 + 1) * 128 + fA + 8]);
        af1[0][2] = packh2(Wf1[k1 * 128 + fA],     Wf1[(k1 + 1) * 128 + fA]);
        af1[0][3] = packh2(Wf1[k1 * 128 + fA + 8], Wf1[(k1 + 1) * 128 + fA + 8]);
        int k2_ = 16 + 2 * lr;   // valid only if < 20
        af1[1][0] = (k2_ < NRBF) ? packh2(Wf1[k2_ * 128 + fA],     Wf1[(k2_ + 1) * 128 + fA]) : 0u;
        af1[1][1] = (k2_ < NRBF) ? packh2(Wf1[k2_ * 128 + fA + 8], Wf1[(k2_ + 1) * 128 + fA + 8]) : 0u;
        af1[1][2] = 0u;
        af1[1][3] = 0u;
    }
    float blo = bf1[fA], bhi = bf1[fA + 8];
    int k2lo = fA >> 1;           // = w*8 + (lq>>1)
    int par = fA & 1;

    int nTiles = nPairs >> 6;
    for (int tile = blockIdx.x; tile < nTiles; tile += gridDim.x) {
        size_t e0g = (size_t)tile << 6;
        __syncthreads();  // prev tile fully done (epilogue reads of sW / sRc etc.)
        // load f_ij as fp16 pairs: sF2[kp][e], kp in [0,10)
        for (int i = t; i < 640; i += 256) {
            int e = i / 10, kp = i % 10;
            float2 v = *(const float2*)(f_ij + (e0g + e) * NRBF + 2 * kp);
            sF2[kp * 72 + e] = packh2(v.x, v.y);
        }
        if (t < 64) {
            sRc[t] = rcut[e0g + t];
            sII[t] = idx_i[e0g + t];
            sJJ[t] = idx_j[e0g + t];
        }
        __syncthreads();
        // ---- phase 1: hidden = ssp(f @ Wf1 + bf1), fp16 mma, store fp16 into H2 ----
#pragma unroll
        for (int nt = 0; nt < 8; nt++) {
            float a4[4] = {0.f, 0.f, 0.f, 0.f};
            int n = 8 * nt + lq;
            uint32_t b00 = sF2[lr * 72 + n];
            uint32_t b01 = sF2[(4 + lr) * 72 + n];
            mma_f16(a4, af1[0], b00, b01);
            uint32_t b10 = sF2[(8 + lr) * 72 + n];
            uint32_t b11 = sF2[(12 + lr) * 72 + n];
            mma_f16(a4, af1[1], b10, b11);
            int e0 = nt * 8 + 2 * lr;
            Hh[(k2lo * 72 + e0) * 2 + par]           = __float2half_rn(sspf(a4[0] + blo));
            Hh[(k2lo * 72 + e0 + 1) * 2 + par]       = __float2half_rn(sspf(a4[1] + blo));
            Hh[((k2lo + 4) * 72 + e0) * 2 + par]     = __float2half_rn(sspf(a4[2] + bhi));
            Hh[((k2lo + 4) * 72 + e0 + 1) * 2 + par] = __float2half_rn(sspf(a4[3] + bhi));
        }
        __syncthreads();
        // ---- phase 2: Wij = hidden @ Wf2, 8nt x 8s fp16 mma ----
        float acc[8][4];
#pragma unroll
        for (int nt = 0; nt < 8; nt++)
#pragma unroll
            for (int c = 0; c < 4; c++) acc[nt][c] = 0.0f;
#pragma unroll
        for (int s = 0; s < 8; s++) {
            int rb0 = (8 * s + lr) * 72 + lq;
            int rb1 = rb0 + 288;  // (8s+4+lr)*72
#pragma unroll
            for (int nt = 0; nt < 8; nt++) {
                uint32_t b0 = H2w[rb0 + 8 * nt];
                uint32_t b1 = H2w[rb1 + 8 * nt];
                mma_f16(acc[nt], af[s], b0, b1);
            }
        }
        __syncthreads();  // all H2 reads done before overwrite as sW
        // ---- writeback fragments -> sW[e][f] (stride 132) ----
#pragma unroll
        for (int nt = 0; nt < 8; nt++) {
            int eb = nt * 8 + 2 * lr;
            sW[eb * 132 + fA]           = acc[nt][0];
            sW[(eb + 1) * 132 + fA]     = acc[nt][1];
            sW[eb * 132 + fA + 8]       = acc[nt][2];
            sW[(eb + 1) * 132 + fA + 8] = acc[nt][3];
        }
        __syncthreads();
        // ---- epilogue: (Wij + bf2) * rc * h[jj] -> RED agg[ii] ----
        {
            int el = t & 63, q = t >> 6;
            float rc = sRc[el];
            int jj = sJJ[el], ii = sII[el];
            const float4* hp = (const float4*)(g_h + (size_t)jj * 128) + q * 8;
            float* ap = g_agg + (size_t)ii * 128 + q * 32;
            const float* wrow = sW + el * 132 + q * 32;
            const float4* b2 = (const float4*)(sBf2 + q * 32);
#pragma unroll
            for (int i = 0; i < 8; i++) {
                float4 wv = *(const float4*)(wrow + 4 * i);
                float4 hv = hp[i];
                float4 bv = b2[i];
                red4(ap + 4 * i, make_float4((wv.x + bv.x) * rc * hv.x,
                                             (wv.y + bv.y) * rc * hv.y,
                                             (wv.z + bv.z) * rc * hv.z,
                                             (wv.w + bv.w) * rc * hv.w));
            }
        }
    }
}

// ---------- k_out: out = ssp(agg@Wo1+bo1)@Wo2+bo2 (tf32 mma, unchanged from R9) ----------
__global__ void __launch_bounds__(512) k_out(const float* __restrict__ Wo1,
                                             const float* __restrict__ bo1,
                                             const float* __restrict__ Wo2,
                                             const float* __restrict__ bo2,
                                             float* __restrict__ out, int nRows) {
    extern __shared__ float sm[];
    int t = threadIdx.x;
    int w = t >> 5, lane = t & 31;
    int lq = lane >> 2, lr = lane & 3;
    int fgrp = w & 7, ahalf = w >> 3;
    int fA = fgrp * 16 + lq;

    int p2_lo = (2 * fgrp) * S_STRIDE + 2 * (lq & 3) + (lq >> 2);
    int p2_hi = p2_lo + S_STRIDE;

    float bo1_lo = __ldg(bo1 + fA), bo1_hi = __ldg(bo1 + fA + 8);
    float bo2_lo = __ldg(bo2 + fA), bo2_hi = __ldg(bo2 + fA + 8);

    const float2* bbase = (const float2*)sm + lane;

    int nTiles = (nRows + 127) >> 7;
    for (int tile = blockIdx.x; tile < nTiles; tile += gridDim.x) {
        int r0 = tile << 7;
        __syncthreads();
        for (int idx = t; idx < 4096; idx += 512) {
            int atom = idx >> 5, kq = idx & 31;
            int row = r0 + atom;
            float4 v = (row < nRows) ? ((const float4*)(g_agg + (size_t)row * 128))[kq]
                                     : make_float4(0.f, 0.f, 0.f, 0.f);
            int base = (atom >> 3) * NT_STRIDE + (kq >> 1) * S_STRIDE + 8 * (atom & 7) + (kq & 1);
            sm[base + 0] = __uint_as_float(tf32c(v.x));
            sm[base + 2] = __uint_as_float(tf32c(v.y));
            sm[base + 4] = __uint_as_float(tf32c(v.z));
            sm[base + 6] = __uint_as_float(tf32c(v.w));
        }
        uint32_t af[16][4];
#pragma unroll
        for (int s = 0; s < 16; s++) {
            af[s][0] = tf32c(__ldg(Wo1 + (8 * s + lr) * 128 + fA));
            af[s][1] = tf32c(__ldg(Wo1 + (8 * s + lr) * 128 + fA + 8));
            af[s][2] = tf32c(__ldg(Wo1 + (8 * s + 4 + lr) * 128 + fA));
            af[s][3] = tf32c(__ldg(Wo1 + (8 * s + 4 + lr) * 128 + fA + 8));
        }
        __syncthreads();
        float acc[8][4];
#pragma unroll
        for (int nt = 0; nt < 8; nt++) {
            acc[nt][0] = bo1_lo; acc[nt][1] = bo1_lo;
            acc[nt][2] = bo1_hi; acc[nt][3] = bo1_hi;
        }
#pragma unroll
        for (int nt = 0; nt < 8; nt++) {
            int gnt = ahalf * 8 + nt;
            const float2* bp = bbase + gnt * (NT_STRIDE / 2);
#pragma unroll
            for (int s = 0; s < 16; s++) {
                float2 bb = bp[s * (S_STRIDE / 2)];
                mma_tf32(acc[nt], af[s], __float_as_uint(bb.x), __float_as_uint(bb.y));
            }
        }
        __syncthreads();
#pragma unroll
        for (int nt = 0; nt < 8; nt++) {
            int gnt = ahalf * 8 + nt;
            float* base = sm + gnt * NT_STRIDE;
            int e0 = 2 * lr;
            base[p2_lo + e0 * 8]       = __uint_as_float(tf32c(sspf(acc[nt][0])));
            base[p2_lo + (e0 + 1) * 8] = __uint_as_float(tf32c(sspf(acc[nt][1])));
            base[p2_hi + e0 * 8]       = __uint_as_float(tf32c(sspf(acc[nt][2])));
            base[p2_hi + (e0 + 1) * 8] = __uint_as_float(tf32c(sspf(acc[nt][3])));
        }
#pragma unroll
        for (int s = 0; s < 16; s++) {
            af[s][0] = tf32c(__ldg(Wo2 + (8 * s + lr) * 128 + fA));
            af[s][1] = tf32c(__ldg(Wo2 + (8 * s + lr) * 128 + fA + 8));
            af[s][2] = tf32c(__ldg(Wo2 + (8 * s + 4 + lr) * 128 + fA));
            af[s][3] = tf32c(__ldg(Wo2 + (8 * s + 4 + lr) * 128 + fA + 8));
        }
        __syncthreads();
#pragma unroll
        for (int nt = 0; nt < 8; nt++) {
            acc[nt][0] = bo2_lo; acc[nt][1] = bo2_lo;
            acc[nt][2] = bo2_hi; acc[nt][3] = bo2_hi;
        }
#pragma unroll
        for (int nt = 0; nt < 8; nt++) {
            int gnt = ahalf * 8 + nt;
            const float2* bp = bbase + gnt * (NT_STRIDE / 2);
#pragma unroll
            for (int s = 0; s < 16; s++) {
                float2 bb = bp[s * (S_STRIDE / 2)];
                mma_tf32(acc[nt], af[s], __float_as_uint(bb.x), __float_as_uint(bb.y));
            }
        }
#pragma unroll
        for (int nt = 0; nt < 8; nt++) {
            int gnt = ahalf * 8 + nt;
            int row0 = r0 + gnt * 8 + 2 * lr;
            if (row0 < nRows) {
                out[(size_t)row0 * 128 + fA] = acc[nt][0];
                out[(size_t)row0 * 128 + fA + 8] = acc[nt][2];
            }
            if (row0 + 1 < nRows) {
                out[(size_t)(row0 + 1) * 128 + fA] = acc[nt][1];
                out[(size_t)(row0 + 1) * 128 + fA + 8] = acc[nt][3];
            }
        }
    }
}

// ---------- launch ----------
extern "C" void kernel_launch(void* const* d_in, const int* in_sizes, int n_in,
                              void* d_out, int out_size) {
    const float* x    = (const float*)d_in[0];
    const float* f_ij = (const float*)d_in[1];
    const float* rcut = (const float*)d_in[2];
    const float* W_in = (const float*)d_in[3];
    const float* b_in = (const float*)d_in[4];
    const float* Wf1  = (const float*)d_in[5];
    const float* bf1  = (const float*)d_in[6];
    const float* Wf2  = (const float*)d_in[7];
    const float* bf2  = (const float*)d_in[8];
    const float* Wo1  = (const float*)d_in[9];
    const float* bo1  = (const float*)d_in[10];
    const float* Wo2  = (const float*)d_in[11];
    const float* bo2  = (const float*)d_in[12];
    const int* idx_i  = (const int*)d_in[13];
    const int* idx_j  = (const int*)d_in[14];
    float* out = (float*)d_out;

    int nAtoms = in_sizes[0] / 128;
    int nPairs = in_sizes[2];

    const int SMEM_INOUT = SH_OUT * 4;       // 73728
    const int SMEM_EDGE  = EW_TOTAL * 4;     // 39680

    cudaFuncSetAttribute(k_in, cudaFuncAttributeMaxDynamicSharedMemorySize, SMEM_INOUT);
    cudaFuncSetAttribute(k_edge, cudaFuncAttributeMaxDynamicSharedMemorySize, SMEM_EDGE);
    cudaFuncSetAttribute(k_out, cudaFuncAttributeMaxDynamicSharedMemorySize, SMEM_INOUT);

    int rowTiles = (nAtoms + 127) / 128;
    k_in<<<rowTiles, 512, SMEM_INOUT>>>(x, W_in, b_in, nAtoms);
    k_edge<<<296, 256, SMEM_EDGE>>>(f_ij, rcut, idx_i, idx_j, Wf1, bf1, Wf2, bf2, nPairs);
    k_out<<<rowTiles, 512, SMEM_INOUT>>>(Wo1, bo1, Wo2, bo2, out, nAtoms);
}

// round 11
// speedup vs baseline: 3.9249x; 1.4106x over previous
#include <cuda_runtime.h>
#include <cuda_bf16.h>
#include <cuda_fp16.h>
#include <cstdint>

typedef unsigned long long ull;

#define F128 128
#define NRBF 20
#define MAX_ATOMS 50000

// k_in / k_out fragment-ordered geometry (tf32 path)
#define S_STRIDE 72
#define NT_STRIDE (16 * S_STRIDE)    // 1152
#define SH_OUT (16 * NT_STRIDE)      // 18432 floats

// k_edge smem word offsets (32-bit words)
#define EW_SW 0            // sW: 64*132 = 8448 words (fp32), aliases H2 (fp16x2)
#define EW_F2 8448         // sF2: 16*72 = 1152 words (fp16x2 pairs)
#define EW_RC 9600         // 64
#define EW_II 9664         // 64
#define EW_JJ 9728         // 64
#define EW_TOTAL 9792

__device__ float g_h[(size_t)MAX_ATOMS * F128];
__device__ float g_agg[(size_t)MAX_ATOMS * F128];

// ---------- helpers ----------
__device__ __forceinline__ void red4(float* p, float4 v) {
    asm volatile("red.global.add.v4.f32 [%0], {%1,%2,%3,%4};" :: "l"(p), "f"(v.x), "f"(v.y), "f"(v.z), "f"(v.w) : "memory");
}
__device__ __forceinline__ float sspf(float x) {
    float e = __expf(-fabsf(x));
    return fmaxf(x, 0.0f) + __logf(1.0f + e) - 0.69314718056f;
}
__device__ __forceinline__ uint32_t tf32c(float f) {
    uint32_t u; asm("cvt.rna.tf32.f32 %0, %1;" : "=r"(u) : "f"(f)); return u;
}
__device__ __forceinline__ uint32_t packh2(float lo, float hi) {
    __half2 h = __floats2half2_rn(lo, hi);   // .x = lo
    return *reinterpret_cast<uint32_t*>(&h);
}
__device__ __forceinline__ void mma_tf32(float d[4], const uint32_t a[4], uint32_t b0, uint32_t b1) {
    asm volatile(
        "mma.sync.aligned.m16n8k8.row.col.f32.tf32.tf32.f32 "
        "{%0,%1,%2,%3}, {%4,%5,%6,%7}, {%8,%9}, {%0,%1,%2,%3};"
        : "+f"(d[0]), "+f"(d[1]), "+f"(d[2]), "+f"(d[3])
        : "r"(a[0]), "r"(a[1]), "r"(a[2]), "r"(a[3]), "r"(b0), "r"(b1));
}
__device__ __forceinline__ void mma_f16(float d[4], const uint32_t a[4], uint32_t b0, uint32_t b1) {
    asm volatile(
        "mma.sync.aligned.m16n8k16.row.col.f32.f16.f16.f32 "
        "{%0,%1,%2,%3}, {%4,%5,%6,%7}, {%8,%9}, {%0,%1,%2,%3};"
        : "+f"(d[0]), "+f"(d[1]), "+f"(d[2]), "+f"(d[3])
        : "r"(a[0]), "r"(a[1]), "r"(a[2]), "r"(a[3]), "r"(b0), "r"(b1));
}

// ---------- k_in: h = x @ W_in + b_in, plus zero g_agg ----------
__global__ void __launch_bounds__(512) k_in(const float* __restrict__ x,
                                            const float* __restrict__ W,
                                            const float* __restrict__ b, int nRows) {
    extern __shared__ float sm[];
    int t = threadIdx.x;
    int w = t >> 5, lane = t & 31;
    int lq = lane >> 2, lr = lane & 3;
    int fgrp = w & 7, ahalf = w >> 3;
    int fA = fgrp * 16 + lq;

    {
        size_t total4 = (size_t)nRows * 32;
        for (size_t i = (size_t)blockIdx.x * blockDim.x + t; i < total4;
             i += (size_t)gridDim.x * blockDim.x)
            ((float4*)g_agg)[i] = make_float4(0.f, 0.f, 0.f, 0.f);
    }

    uint32_t af[16][4];
#pragma unroll
    for (int s = 0; s < 16; s++) {
        af[s][0] = tf32c(__ldg(W + (8 * s + lr) * 128 + fA));
        af[s][1] = tf32c(__ldg(W + (8 * s + lr) * 128 + fA + 8));
        af[s][2] = tf32c(__ldg(W + (8 * s + 4 + lr) * 128 + fA));
        af[s][3] = tf32c(__ldg(W + (8 * s + 4 + lr) * 128 + fA + 8));
    }
    float b_lo = __ldg(b + fA), b_hi = __ldg(b + fA + 8);

    int nTiles = (nRows + 127) >> 7;
    for (int tile = blockIdx.x; tile < nTiles; tile += gridDim.x) {
        int r0 = tile << 7;
        __syncthreads();
        for (int idx = t; idx < 4096; idx += 512) {
            int atom = idx >> 5, kq = idx & 31;
            int row = r0 + atom;
            float4 v = (row < nRows) ? ((const float4*)(x + (size_t)row * 128))[kq]
                                     : make_float4(0.f, 0.f, 0.f, 0.f);
            int base = (atom >> 3) * NT_STRIDE + (kq >> 1) * S_STRIDE + 8 * (atom & 7) + (kq & 1);
            sm[base + 0] = __uint_as_float(tf32c(v.x));
            sm[base + 2] = __uint_as_float(tf32c(v.y));
            sm[base + 4] = __uint_as_float(tf32c(v.z));
            sm[base + 6] = __uint_as_float(tf32c(v.w));
        }
        __syncthreads();
        float acc[8][4];
#pragma unroll
        for (int nt = 0; nt < 8; nt++) {
            acc[nt][0] = b_lo; acc[nt][1] = b_lo;
            acc[nt][2] = b_hi; acc[nt][3] = b_hi;
        }
        const float2* bbase = (const float2*)sm + lane;
#pragma unroll
        for (int nt = 0; nt < 8; nt++) {
            int gnt = ahalf * 8 + nt;
            const float2* bp = bbase + gnt * (NT_STRIDE / 2);
#pragma unroll
            for (int s = 0; s < 16; s++) {
                float2 bb = bp[s * (S_STRIDE / 2)];
                mma_tf32(acc[nt], af[s], __float_as_uint(bb.x), __float_as_uint(bb.y));
            }
        }
#pragma unroll
        for (int nt = 0; nt < 8; nt++) {
            int gnt = ahalf * 8 + nt;
            int row0 = r0 + gnt * 8 + 2 * lr;
            if (row0 < nRows) {
                g_h[(size_t)row0 * 128 + fA] = acc[nt][0];
                g_h[(size_t)row0 * 128 + fA + 8] = acc[nt][2];
            }
            if (row0 + 1 < nRows) {
                g_h[(size_t)(row0 + 1) * 128 + fA] = acc[nt][1];
                g_h[(size_t)(row0 + 1) * 128 + fA + 8] = acc[nt][3];
            }
        }
    }
}

// ---------- fused edge pipeline: fp16 mma + row-per-warp epilogue ----------
__global__ void __launch_bounds__(256, 2) k_edge(const float* __restrict__ f_ij,
                                                 const float* __restrict__ rcut,
                                                 const int* __restrict__ idx_i,
                                                 const int* __restrict__ idx_j,
                                                 const float* __restrict__ Wf1,
                                                 const float* __restrict__ bf1,
                                                 const float* __restrict__ Wf2,
                                                 const float* __restrict__ bf2, int nPairs) {
    extern __shared__ float sm[];
    float* sW = sm + EW_SW;                 // fp32 64x132, aliases H2
    uint32_t* H2w = (uint32_t*)(sm + EW_SW);  // fp16x2 words: [k2][n], stride 72
    __half* Hh = (__half*)(sm + EW_SW);
    uint32_t* sF2 = (uint32_t*)(sm + EW_F2);  // fp16x2 [kp][e], stride 72
    float* sRc = sm + EW_RC;
    int* sII = (int*)(sm + EW_II);
    int* sJJ = (int*)(sm + EW_JJ);

    int t = threadIdx.x;
    int w = t >> 5, lane = t & 31;
    int lq = lane >> 2, lr = lane & 3;

    // zero sF2 pads (kp 10..15) once
    for (int i = t; i < 432; i += 256) sF2[720 + i] = 0;

    // per-lane bf2 (epilogue covers floats 4*lane..4*lane+3)
    float4 bf2v = ((const float4*)bf2)[lane];

    int fA = w * 16 + lq;
    // phase-2 A fragments: A[f][k] = Wf2[k*128+f], fp16 pairs, 8 chunks of k16
    uint32_t af[8][4];
#pragma unroll
    for (int s = 0; s < 8; s++) {
        int k0 = 16 * s + 2 * lr, k1 = 16 * s + 8 + 2 * lr;
        af[s][0] = packh2(Wf2[k0 * 128 + fA],     Wf2[(k0 + 1) * 128 + fA]);
        af[s][1] = packh2(Wf2[k0 * 128 + fA + 8], Wf2[(k0 + 1) * 128 + fA + 8]);
        af[s][2] = packh2(Wf2[k1 * 128 + fA],     Wf2[(k1 + 1) * 128 + fA]);
        af[s][3] = packh2(Wf2[k1 * 128 + fA + 8], Wf2[(k1 + 1) * 128 + fA + 8]);
    }
    // phase-1 A fragments: K=20 padded to 32 (2 chunks of 16)
    uint32_t af1[2][4];
    {
        int k0 = 2 * lr, k1 = 8 + 2 * lr;
        af1[0][0] = packh2(Wf1[k0 * 128 + fA],     Wf1[(k0 + 1) * 128 + fA]);
        af1[0][1] = packh2(Wf1[k0 * 128 + fA + 8], Wf1[(k0 + 1) * 128 + fA + 8]);
        af1[0][2] = packh2(Wf1[k1 * 128 + fA],     Wf1[(k1 + 1) * 128 + fA]);
        af1[0][3] = packh2(Wf1[k1 * 128 + fA + 8], Wf1[(k1 + 1) * 128 + fA + 8]);
        int k2_ = 16 + 2 * lr;
        af1[1][0] = (k2_ < NRBF) ? packh2(Wf1[k2_ * 128 + fA],     Wf1[(k2_ + 1) * 128 + fA]) : 0u;
        af1[1][1] = (k2_ < NRBF) ? packh2(Wf1[k2_ * 128 + fA + 8], Wf1[(k2_ + 1) * 128 + fA + 8]) : 0u;
        af1[1][2] = 0u;
        af1[1][3] = 0u;
    }
    float blo = bf1[fA], bhi = bf1[fA + 8];
    int k2lo = fA >> 1;
    int par = fA & 1;

    int nTiles = nPairs >> 6;
    for (int tile = blockIdx.x; tile < nTiles; tile += gridDim.x) {
        size_t e0g = (size_t)tile << 6;
        __syncthreads();  // prev tile fully done
        // load f_ij as fp16 pairs: sF2[kp][e], kp in [0,10)
        for (int i = t; i < 640; i += 256) {
            int e = i / 10, kp = i % 10;
            float2 v = *(const float2*)(f_ij + (e0g + e) * NRBF + 2 * kp);
            sF2[kp * 72 + e] = packh2(v.x, v.y);
        }
        if (t < 64) {
            sRc[t] = rcut[e0g + t];
            sII[t] = idx_i[e0g + t];
            sJJ[t] = idx_j[e0g + t];
        }
        __syncthreads();
        // ---- phase 1: hidden = ssp(f @ Wf1 + bf1), fp16 mma ----
#pragma unroll
        for (int nt = 0; nt < 8; nt++) {
            float a4[4] = {0.f, 0.f, 0.f, 0.f};
            int n = 8 * nt + lq;
            uint32_t b00 = sF2[lr * 72 + n];
            uint32_t b01 = sF2[(4 + lr) * 72 + n];
            mma_f16(a4, af1[0], b00, b01);
            uint32_t b10 = sF2[(8 + lr) * 72 + n];
            uint32_t b11 = sF2[(12 + lr) * 72 + n];
            mma_f16(a4, af1[1], b10, b11);
            int e0 = nt * 8 + 2 * lr;
            Hh[(k2lo * 72 + e0) * 2 + par]           = __float2half_rn(sspf(a4[0] + blo));
            Hh[(k2lo * 72 + e0 + 1) * 2 + par]       = __float2half_rn(sspf(a4[1] + blo));
            Hh[((k2lo + 4) * 72 + e0) * 2 + par]     = __float2half_rn(sspf(a4[2] + bhi));
            Hh[((k2lo + 4) * 72 + e0 + 1) * 2 + par] = __float2half_rn(sspf(a4[3] + bhi));
        }
        __syncthreads();
        // ---- phase 2: Wij = hidden @ Wf2 ----
        float acc[8][4];
#pragma unroll
        for (int nt = 0; nt < 8; nt++)
#pragma unroll
            for (int c = 0; c < 4; c++) acc[nt][c] = 0.0f;
#pragma unroll
        for (int s = 0; s < 8; s++) {
            int rb0 = (8 * s + lr) * 72 + lq;
            int rb1 = rb0 + 288;
#pragma unroll
            for (int nt = 0; nt < 8; nt++) {
                uint32_t b0 = H2w[rb0 + 8 * nt];
                uint32_t b1 = H2w[rb1 + 8 * nt];
                mma_f16(acc[nt], af[s], b0, b1);
            }
        }
        __syncthreads();  // all H2 reads done before overwrite as sW
        // ---- writeback fragments -> sW[e][f] (stride 132) ----
#pragma unroll
        for (int nt = 0; nt < 8; nt++) {
            int eb = nt * 8 + 2 * lr;
            sW[eb * 132 + fA]           = acc[nt][0];
            sW[(eb + 1) * 132 + fA]     = acc[nt][1];
            sW[eb * 132 + fA + 8]       = acc[nt][2];
            sW[(eb + 1) * 132 + fA + 8] = acc[nt][3];
        }
        __syncthreads();
        // ---- epilogue: one edge row per warp iteration ----
        // lane covers floats 4*lane..4*lane+3 of the row: gather + RED touch
        // 4 cache lines per warp-instruction instead of 32.
        {
            int e0 = w * 8;
#pragma unroll 4
            for (int k = 0; k < 8; k++) {
                int e = e0 + k;
                float rc = sRc[e];
                int jj = sJJ[e], ii = sII[e];
                float4 hv = ((const float4*)(g_h + (size_t)jj * 128))[lane];
                float4 wv = *(const float4*)(sW + e * 132 + 4 * lane);
                red4(g_agg + (size_t)ii * 128 + 4 * lane,
                     make_float4((wv.x + bf2v.x) * rc * hv.x,
                                 (wv.y + bf2v.y) * rc * hv.y,
                                 (wv.z + bf2v.z) * rc * hv.z,
                                 (wv.w + bf2v.w) * rc * hv.w));
            }
        }
    }
}

// ---------- k_out: out = ssp(agg@Wo1+bo1)@Wo2+bo2 (tf32 mma) ----------
__global__ void __launch_bounds__(512) k_out(const float* __restrict__ Wo1,
                                             const float* __restrict__ bo1,
                                             const float* __restrict__ Wo2,
                                             const float* __restrict__ bo2,
                                             float* __restrict__ out, int nRows) {
    extern __shared__ float sm[];
    int t = threadIdx.x;
    int w = t >> 5, lane = t & 31;
    int lq = lane >> 2, lr = lane & 3;
    int fgrp = w & 7, ahalf = w >> 3;
    int fA = fgrp * 16 + lq;

    int p2_lo = (2 * fgrp) * S_STRIDE + 2 * (lq & 3) + (lq >> 2);
    int p2_hi = p2_lo + S_STRIDE;

    float bo1_lo = __ldg(bo1 + fA), bo1_hi = __ldg(bo1 + fA + 8);
    float bo2_lo = __ldg(bo2 + fA), bo2_hi = __ldg(bo2 + fA + 8);

    const float2* bbase = (const float2*)sm + lane;

    int nTiles = (nRows + 127) >> 7;
    for (int tile = blockIdx.x; tile < nTiles; tile += gridDim.x) {
        int r0 = tile << 7;
        __syncthreads();
        for (int idx = t; idx < 4096; idx += 512) {
            int atom = idx >> 5, kq = idx & 31;
            int row = r0 + atom;
            float4 v = (row < nRows) ? ((const float4*)(g_agg + (size_t)row * 128))[kq]
                                     : make_float4(0.f, 0.f, 0.f, 0.f);
            int base = (atom >> 3) * NT_STRIDE + (kq >> 1) * S_STRIDE + 8 * (atom & 7) + (kq & 1);
            sm[base + 0] = __uint_as_float(tf32c(v.x));
            sm[base + 2] = __uint_as_float(tf32c(v.y));
            sm[base + 4] = __uint_as_float(tf32c(v.z));
            sm[base + 6] = __uint_as_float(tf32c(v.w));
        }
        uint32_t af[16][4];
#pragma unroll
        for (int s = 0; s < 16; s++) {
            af[s][0] = tf32c(__ldg(Wo1 + (8 * s + lr) * 128 + fA));
            af[s][1] = tf32c(__ldg(Wo1 + (8 * s + lr) * 128 + fA + 8));
            af[s][2] = tf32c(__ldg(Wo1 + (8 * s + 4 + lr) * 128 + fA));
            af[s][3] = tf32c(__ldg(Wo1 + (8 * s + 4 + lr) * 128 + fA + 8));
        }
        __syncthreads();
        float acc[8][4];
#pragma unroll
        for (int nt = 0; nt < 8; nt++) {
            acc[nt][0] = bo1_lo; acc[nt][1] = bo1_lo;
            acc[nt][2] = bo1_hi; acc[nt][3] = bo1_hi;
        }
#pragma unroll
        for (int nt = 0; nt < 8; nt++) {
            int gnt = ahalf * 8 + nt;
            const float2* bp = bbase + gnt * (NT_STRIDE / 2);
#pragma unroll
            for (int s = 0; s < 16; s++) {
                float2 bb = bp[s * (S_STRIDE / 2)];
                mma_tf32(acc[nt], af[s], __float_as_uint(bb.x), __float_as_uint(bb.y));
            }
        }
        __syncthreads();
#pragma unroll
        for (int nt = 0; nt < 8; nt++) {
            int gnt = ahalf * 8 + nt;
            float* base = sm + gnt * NT_STRIDE;
            int e0 = 2 * lr;
            base[p2_lo + e0 * 8]       = __uint_as_float(tf32c(sspf(acc[nt][0])));
            base[p2_lo + (e0 + 1) * 8] = __uint_as_float(tf32c(sspf(acc[nt][1])));
            base[p2_hi + e0 * 8]       = __uint_as_float(tf32c(sspf(acc[nt][2])));
            base[p2_hi + (e0 + 1) * 8] = __uint_as_float(tf32c(sspf(acc[nt][3])));
        }
#pragma unroll
        for (int s = 0; s < 16; s++) {
            af[s][0] = tf32c(__ldg(Wo2 + (8 * s + lr) * 128 + fA));
            af[s][1] = tf32c(__ldg(Wo2 + (8 * s + lr) * 128 + fA + 8));
            af[s][2] = tf32c(__ldg(Wo2 + (8 * s + 4 + lr) * 128 + fA));
            af[s][3] = tf32c(__ldg(Wo2 + (8 * s + 4 + lr) * 128 + fA + 8));
        }
        __syncthreads();
#pragma unroll
        for (int nt = 0; nt < 8; nt++) {
            acc[nt][0] = bo2_lo; acc[nt][1] = bo2_lo;
            acc[nt][2] = bo2_hi; acc[nt][3] = bo2_hi;
        }
#pragma unroll
        for (int nt = 0; nt < 8; nt++) {
            int gnt = ahalf * 8 + nt;
            const float2* bp = bbase + gnt * (NT_STRIDE / 2);
#pragma unroll
            for (int s = 0; s < 16; s++) {
                float2 bb = bp[s * (S_STRIDE / 2)];
                mma_tf32(acc[nt], af[s], __float_as_uint(bb.x), __float_as_uint(bb.y));
            }
        }
#pragma unroll
        for (int nt = 0; nt < 8; nt++) {
            int gnt = ahalf * 8 + nt;
            int row0 = r0 + gnt * 8 + 2 * lr;
            if (row0 < nRows) {
                out[(size_t)row0 * 128 + fA] = acc[nt][0];
                out[(size_t)row0 * 128 + fA + 8] = acc[nt][2];
            }
            if (row0 + 1 < nRows) {
                out[(size_t)(row0 + 1) * 128 + fA] = acc[nt][1];
                out[(size_t)(row0 + 1) * 128 + fA + 8] = acc[nt][3];
            }
        }
    }
}

// ---------- launch ----------
extern "C" void kernel_launch(void* const* d_in, const int* in_sizes, int n_in,
                              void* d_out, int out_size) {
    const float* x    = (const float*)d_in[0];
    const float* f_ij = (const float*)d_in[1];
    const float* rcut = (const float*)d_in[2];
    const float* W_in = (const float*)d_in[3];
    const float* b_in = (const float*)d_in[4];
    const float* Wf1  = (const float*)d_in[5];
    const float* bf1  = (const float*)d_in[6];
    const float* Wf2  = (const float*)d_in[7];
    const float* bf2  = (const float*)d_in[8];
    const float* Wo1  = (const float*)d_in[9];
    const float* bo1  = (const float*)d_in[10];
    const float* Wo2  = (const float*)d_in[11];
    const float* bo2  = (const float*)d_in[12];
    const int* idx_i  = (const int*)d_in[13];
    const int* idx_j  = (const int*)d_in[14];
    float* out = (float*)d_out;

    int nAtoms = in_sizes[0] / 128;
    int nPairs = in_sizes[2];

    const int SMEM_INOUT = SH_OUT * 4;       // 73728
    const int SMEM_EDGE  = EW_TOTAL * 4;     // 39168

    cudaFuncSetAttribute(k_in, cudaFuncAttributeMaxDynamicSharedMemorySize, SMEM_INOUT);
    cudaFuncSetAttribute(k_edge, cudaFuncAttributeMaxDynamicSharedMemorySize, SMEM_EDGE);
    cudaFuncSetAttribute(k_out, cudaFuncAttributeMaxDynamicSharedMemorySize, SMEM_INOUT);

    int rowTiles = (nAtoms + 127) / 128;
    k_in<<<rowTiles, 512, SMEM_INOUT>>>(x, W_in, b_in, nAtoms);
    k_edge<<<296, 256, SMEM_EDGE>>>(f_ij, rcut, idx_i, idx_j, Wf1, bf1, Wf2, bf2, nPairs);
    k_out<<<rowTiles, 512, SMEM_INOUT>>>(Wo1, bo1, Wo2, bo2, out, nAtoms);
}

// round 12
// speedup vs baseline: 4.8859x; 1.2449x over previous
#include <cuda_runtime.h>
#include <cuda_bf16.h>
#include <cuda_fp16.h>
#include <cstdint>

typedef unsigned long long ull;

#define F128 128
#define NRBF 20
#define MAX_ATOMS 50000

// k_in / k_out fragment-ordered geometry (tf32 path)
#define S_STRIDE 72
#define NT_STRIDE (16 * S_STRIDE)    // 1152
#define SH_OUT (16 * NT_STRIDE)      // 18432 floats

// k_edge smem word offsets (32-bit words)
#define EW_SW 0            // sW: 64*132 = 8448 words (fp32), aliases H2 (fp16x2)
#define EW_F2 8448         // sF2: 16*72 = 1152 words (fp16x2 pairs)
#define EW_RC 9600         // 64
#define EW_II 9664         // 64
#define EW_JJ 9728         // 64
#define EW_TOTAL 9792

__device__ float g_h[(size_t)MAX_ATOMS * F128];
__device__ float g_agg[(size_t)MAX_ATOMS * F128];

// ---------- helpers ----------
__device__ __forceinline__ void red4(float* p, float4 v) {
    asm volatile("red.global.add.v4.f32 [%0], {%1,%2,%3,%4};" :: "l"(p), "f"(v.x), "f"(v.y), "f"(v.z), "f"(v.w) : "memory");
}
__device__ __forceinline__ float sspf(float x) {
    float e = __expf(-fabsf(x));
    return fmaxf(x, 0.0f) + __logf(1.0f + e) - 0.69314718056f;
}
__device__ __forceinline__ uint32_t tf32c(float f) {
    uint32_t u; asm("cvt.rna.tf32.f32 %0, %1;" : "=r"(u) : "f"(f)); return u;
}
__device__ __forceinline__ uint32_t packh2(float lo, float hi) {
    __half2 h = __floats2half2_rn(lo, hi);   // .x = lo
    return *reinterpret_cast<uint32_t*>(&h);
}
__device__ __forceinline__ void mma_tf32(float d[4], const uint32_t a[4], uint32_t b0, uint32_t b1) {
    asm volatile(
        "mma.sync.aligned.m16n8k8.row.col.f32.tf32.tf32.f32 "
        "{%0,%1,%2,%3}, {%4,%5,%6,%7}, {%8,%9}, {%0,%1,%2,%3};"
        : "+f"(d[0]), "+f"(d[1]), "+f"(d[2]), "+f"(d[3])
        : "r"(a[0]), "r"(a[1]), "r"(a[2]), "r"(a[3]), "r"(b0), "r"(b1));
}
__device__ __forceinline__ void mma_f16(float d[4], const uint32_t a[4], uint32_t b0, uint32_t b1) {
    asm volatile(
        "mma.sync.aligned.m16n8k16.row.col.f32.f16.f16.f32 "
        "{%0,%1,%2,%3}, {%4,%5,%6,%7}, {%8,%9}, {%0,%1,%2,%3};"
        : "+f"(d[0]), "+f"(d[1]), "+f"(d[2]), "+f"(d[3])
        : "r"(a[0]), "r"(a[1]), "r"(a[2]), "r"(a[3]), "r"(b0), "r"(b1));
}

// ---------- k_in: h = x @ W_in + b_in, plus zero g_agg ----------
__global__ void __launch_bounds__(512) k_in(const float* __restrict__ x,
                                            const float* __restrict__ W,
                                            const float* __restrict__ b, int nRows) {
    extern __shared__ float sm[];
    int t = threadIdx.x;
    int w = t >> 5, lane = t & 31;
    int lq = lane >> 2, lr = lane & 3;
    int fgrp = w & 7, ahalf = w >> 3;
    int fA = fgrp * 16 + lq;

    {
        size_t total4 = (size_t)nRows * 32;
        for (size_t i = (size_t)blockIdx.x * blockDim.x + t; i < total4;
             i += (size_t)gridDim.x * blockDim.x)
            ((float4*)g_agg)[i] = make_float4(0.f, 0.f, 0.f, 0.f);
    }

    uint32_t af[16][4];
#pragma unroll
    for (int s = 0; s < 16; s++) {
        af[s][0] = tf32c(__ldg(W + (8 * s + lr) * 128 + fA));
        af[s][1] = tf32c(__ldg(W + (8 * s + lr) * 128 + fA + 8));
        af[s][2] = tf32c(__ldg(W + (8 * s + 4 + lr) * 128 + fA));
        af[s][3] = tf32c(__ldg(W + (8 * s + 4 + lr) * 128 + fA + 8));
    }
    float b_lo = __ldg(b + fA), b_hi = __ldg(b + fA + 8);

    int nTiles = (nRows + 127) >> 7;
    for (int tile = blockIdx.x; tile < nTiles; tile += gridDim.x) {
        int r0 = tile << 7;
        __syncthreads();
        for (int idx = t; idx < 4096; idx += 512) {
            int atom = idx >> 5, kq = idx & 31;
            int row = r0 + atom;
            float4 v = (row < nRows) ? ((const float4*)(x + (size_t)row * 128))[kq]
                                     : make_float4(0.f, 0.f, 0.f, 0.f);
            int base = (atom >> 3) * NT_STRIDE + (kq >> 1) * S_STRIDE + 8 * (atom & 7) + (kq & 1);
            sm[base + 0] = __uint_as_float(tf32c(v.x));
            sm[base + 2] = __uint_as_float(tf32c(v.y));
            sm[base + 4] = __uint_as_float(tf32c(v.z));
            sm[base + 6] = __uint_as_float(tf32c(v.w));
        }
        __syncthreads();
        float acc[8][4];
#pragma unroll
        for (int nt = 0; nt < 8; nt++) {
            acc[nt][0] = b_lo; acc[nt][1] = b_lo;
            acc[nt][2] = b_hi; acc[nt][3] = b_hi;
        }
        const float2* bbase = (const float2*)sm + lane;
#pragma unroll
        for (int nt = 0; nt < 8; nt++) {
            int gnt = ahalf * 8 + nt;
            const float2* bp = bbase + gnt * (NT_STRIDE / 2);
#pragma unroll
            for (int s = 0; s < 16; s++) {
                float2 bb = bp[s * (S_STRIDE / 2)];
                mma_tf32(acc[nt], af[s], __float_as_uint(bb.x), __float_as_uint(bb.y));
            }
        }
#pragma unroll
        for (int nt = 0; nt < 8; nt++) {
            int gnt = ahalf * 8 + nt;
            int row0 = r0 + gnt * 8 + 2 * lr;
            if (row0 < nRows) {
                g_h[(size_t)row0 * 128 + fA] = acc[nt][0];
                g_h[(size_t)row0 * 128 + fA + 8] = acc[nt][2];
            }
            if (row0 + 1 < nRows) {
                g_h[(size_t)(row0 + 1) * 128 + fA] = acc[nt][1];
                g_h[(size_t)(row0 + 1) * 128 + fA + 8] = acc[nt][3];
            }
        }
    }
}

// ---------- fused edge pipeline: fp16 mma + row-per-warp epilogue + prefetch ----------
__global__ void __launch_bounds__(256, 2) k_edge(const float* __restrict__ f_ij,
                                                 const float* __restrict__ rcut,
                                                 const int* __restrict__ idx_i,
                                                 const int* __restrict__ idx_j,
                                                 const float* __restrict__ Wf1,
                                                 const float* __restrict__ bf1,
                                                 const float* __restrict__ Wf2,
                                                 const float* __restrict__ bf2, int nPairs) {
    extern __shared__ float sm[];
    float* sW = sm + EW_SW;                 // fp32 64x132, aliases H2
    uint32_t* H2w = (uint32_t*)(sm + EW_SW);  // fp16x2 words: [k2][n], stride 72
    __half* Hh = (__half*)(sm + EW_SW);
    uint32_t* sF2 = (uint32_t*)(sm + EW_F2);  // fp16x2 [kp][e], stride 72
    float* sRc = sm + EW_RC;
    int* sII = (int*)(sm + EW_II);
    int* sJJ = (int*)(sm + EW_JJ);

    int t = threadIdx.x;
    int w = t >> 5, lane = t & 31;
    int lq = lane >> 2, lr = lane & 3;

    // zero sF2 pads (kp 10..15) once
    for (int i = t; i < 432; i += 256) sF2[720 + i] = 0;

    // per-lane bf2 (epilogue covers floats 4*lane..4*lane+3)
    float4 bf2v = ((const float4*)bf2)[lane];

    int fA = w * 16 + lq;
    // phase-2 A fragments
    uint32_t af[8][4];
#pragma unroll
    for (int s = 0; s < 8; s++) {
        int k0 = 16 * s + 2 * lr, k1 = 16 * s + 8 + 2 * lr;
        af[s][0] = packh2(Wf2[k0 * 128 + fA],     Wf2[(k0 + 1) * 128 + fA]);
        af[s][1] = packh2(Wf2[k0 * 128 + fA + 8], Wf2[(k0 + 1) * 128 + fA + 8]);
        af[s][2] = packh2(Wf2[k1 * 128 + fA],     Wf2[(k1 + 1) * 128 + fA]);
        af[s][3] = packh2(Wf2[k1 * 128 + fA + 8], Wf2[(k1 + 1) * 128 + fA + 8]);
    }
    // phase-1 A fragments
    uint32_t af1[2][4];
    {
        int k0 = 2 * lr, k1 = 8 + 2 * lr;
        af1[0][0] = packh2(Wf1[k0 * 128 + fA],     Wf1[(k0 + 1) * 128 + fA]);
        af1[0][1] = packh2(Wf1[k0 * 128 + fA + 8], Wf1[(k0 + 1) * 128 + fA + 8]);
        af1[0][2] = packh2(Wf1[k1 * 128 + fA],     Wf1[(k1 + 1) * 128 + fA]);
        af1[0][3] = packh2(Wf1[k1 * 128 + fA + 8], Wf1[(k1 + 1) * 128 + fA + 8]);
        int k2_ = 16 + 2 * lr;
        af1[1][0] = (k2_ < NRBF) ? packh2(Wf1[k2_ * 128 + fA],     Wf1[(k2_ + 1) * 128 + fA]) : 0u;
        af1[1][1] = (k2_ < NRBF) ? packh2(Wf1[k2_ * 128 + fA + 8], Wf1[(k2_ + 1) * 128 + fA + 8]) : 0u;
        af1[1][2] = 0u;
        af1[1][3] = 0u;
    }
    float blo = bf1[fA], bhi = bf1[fA + 8];
    int k2lo = fA >> 1;
    int par = fA & 1;

    // prefetch decomposition: fa covers floats 4t..4t+3 of the 1280-float f tile
    // (20 ≡ 0 mod 4 → never straddles an edge row); fb covers 1024+4t.. for t<64.
    int eA = t / 5, kpA = ((4 * t) - eA * 20) >> 1;
    int gi2 = 1024 + 4 * (t & 63);
    int eB = gi2 / 20, kpB = (gi2 - eB * 20) >> 1;

    int nTiles = nPairs >> 6;
    int grid = gridDim.x;

    // first-tile prefetch
    float4 pfa = make_float4(0.f, 0.f, 0.f, 0.f), pfb = pfa;
    float prc = 0.f; int pii = 0, pjj = 0;
    if (blockIdx.x < nTiles) {
        size_t e0g = (size_t)blockIdx.x << 6;
        pfa = *(const float4*)(f_ij + e0g * NRBF + 4 * t);
        if (t < 64) {
            pfb = *(const float4*)(f_ij + e0g * NRBF + gi2);
            prc = rcut[e0g + t];
            pii = idx_i[e0g + t];
            pjj = idx_j[e0g + t];
        }
    }

    for (int tile = blockIdx.x; tile < nTiles; tile += grid) {
        __syncthreads();  // prev tile fully done (epilogue reads of sW/sRc/sII/sJJ)
        // store prefetched edge data
        sF2[kpA * 72 + eA]       = packh2(pfa.x, pfa.y);
        sF2[(kpA + 1) * 72 + eA] = packh2(pfa.z, pfa.w);
        if (t < 64) {
            sF2[kpB * 72 + eB]       = packh2(pfb.x, pfb.y);
            sF2[(kpB + 1) * 72 + eB] = packh2(pfb.z, pfb.w);
            sRc[t] = prc;
            sII[t] = pii;
            sJJ[t] = pjj;
        }
        __syncthreads();
        // ---- phase 1: hidden = ssp(f @ Wf1 + bf1), fp16 mma ----
#pragma unroll
        for (int nt = 0; nt < 8; nt++) {
            float a4[4] = {0.f, 0.f, 0.f, 0.f};
            int n = 8 * nt + lq;
            uint32_t b00 = sF2[lr * 72 + n];
            uint32_t b01 = sF2[(4 + lr) * 72 + n];
            mma_f16(a4, af1[0], b00, b01);
            uint32_t b10 = sF2[(8 + lr) * 72 + n];
            uint32_t b11 = sF2[(12 + lr) * 72 + n];
            mma_f16(a4, af1[1], b10, b11);
            int e0 = nt * 8 + 2 * lr;
            Hh[(k2lo * 72 + e0) * 2 + par]           = __float2half_rn(sspf(a4[0] + blo));
            Hh[(k2lo * 72 + e0 + 1) * 2 + par]       = __float2half_rn(sspf(a4[1] + blo));
            Hh[((k2lo + 4) * 72 + e0) * 2 + par]     = __float2half_rn(sspf(a4[2] + bhi));
            Hh[((k2lo + 4) * 72 + e0 + 1) * 2 + par] = __float2half_rn(sspf(a4[3] + bhi));
        }
        __syncthreads();
        // ---- phase 2: Wij = hidden @ Wf2 ----
        float acc[8][4];
#pragma unroll
        for (int nt = 0; nt < 8; nt++)
#pragma unroll
            for (int c = 0; c < 4; c++) acc[nt][c] = 0.0f;
#pragma unroll
        for (int s = 0; s < 8; s++) {
            int rb0 = (8 * s + lr) * 72 + lq;
            int rb1 = rb0 + 288;
#pragma unroll
            for (int nt = 0; nt < 8; nt++) {
                uint32_t b0 = H2w[rb0 + 8 * nt];
                uint32_t b1 = H2w[rb1 + 8 * nt];
                mma_f16(acc[nt], af[s], b0, b1);
            }
        }
        __syncthreads();  // all H2 reads done before overwrite as sW
        // ---- writeback fragments -> sW[e][f] (stride 132) ----
#pragma unroll
        for (int nt = 0; nt < 8; nt++) {
            int eb = nt * 8 + 2 * lr;
            sW[eb * 132 + fA]           = acc[nt][0];
            sW[(eb + 1) * 132 + fA]     = acc[nt][1];
            sW[eb * 132 + fA + 8]       = acc[nt][2];
            sW[(eb + 1) * 132 + fA + 8] = acc[nt][3];
        }
        // ---- issue NEXT tile's prefetch (overlaps epilogue + barrier) ----
        {
            int ntile = tile + grid;
            if (ntile < nTiles) {
                size_t e0g = (size_t)ntile << 6;
                pfa = *(const float4*)(f_ij + e0g * NRBF + 4 * t);
                if (t < 64) {
                    pfb = *(const float4*)(f_ij + e0g * NRBF + gi2);
                    prc = rcut[e0g + t];
                    pii = idx_i[e0g + t];
                    pjj = idx_j[e0g + t];
                }
            }
        }
        __syncthreads();  // sW writes visible
        // ---- epilogue: one edge row per warp iteration ----
        {
            int e0 = w * 8;
#pragma unroll 4
            for (int k = 0; k < 8; k++) {
                int e = e0 + k;
                float rc = sRc[e];
                int jj = sJJ[e], ii = sII[e];
                float4 hv = ((const float4*)(g_h + (size_t)jj * 128))[lane];
                float4 wv = *(const float4*)(sW + e * 132 + 4 * lane);
                red4(g_agg + (size_t)ii * 128 + 4 * lane,
                     make_float4((wv.x + bf2v.x) * rc * hv.x,
                                 (wv.y + bf2v.y) * rc * hv.y,
                                 (wv.z + bf2v.z) * rc * hv.z,
                                 (wv.w + bf2v.w) * rc * hv.w));
            }
        }
    }
}

// ---------- k_out: out = ssp(agg@Wo1+bo1)@Wo2+bo2 (tf32 mma) ----------
__global__ void __launch_bounds__(512) k_out(const float* __restrict__ Wo1,
                                             const float* __restrict__ bo1,
                                             const float* __restrict__ Wo2,
                                             const float* __restrict__ bo2,
                                             float* __restrict__ out, int nRows) {
    extern __shared__ float sm[];
    int t = threadIdx.x;
    int w = t >> 5, lane = t & 31;
    int lq = lane >> 2, lr = lane & 3;
    int fgrp = w & 7, ahalf = w >> 3;
    int fA = fgrp * 16 + lq;

    int p2_lo = (2 * fgrp) * S_STRIDE + 2 * (lq & 3) + (lq >> 2);
    int p2_hi = p2_lo + S_STRIDE;

    float bo1_lo = __ldg(bo1 + fA), bo1_hi = __ldg(bo1 + fA + 8);
    float bo2_lo = __ldg(bo2 + fA), bo2_hi = __ldg(bo2 + fA + 8);

    const float2* bbase = (const float2*)sm + lane;

    int nTiles = (nRows + 127) >> 7;
    for (int tile = blockIdx.x; tile < nTiles; tile += gridDim.x) {
        int r0 = tile << 7;
        __syncthreads();
        for (int idx = t; idx < 4096; idx += 512) {
            int atom = idx >> 5, kq = idx & 31;
            int row = r0 + atom;
            float4 v = (row < nRows) ? ((const float4*)(g_agg + (size_t)row * 128))[kq]
                                     : make_float4(0.f, 0.f, 0.f, 0.f);
            int base = (atom >> 3) * NT_STRIDE + (kq >> 1) * S_STRIDE + 8 * (atom & 7) + (kq & 1);
            sm[base + 0] = __uint_as_float(tf32c(v.x));
            sm[base + 2] = __uint_as_float(tf32c(v.y));
            sm[base + 4] = __uint_as_float(tf32c(v.z));
            sm[base + 6] = __uint_as_float(tf32c(v.w));
        }
        uint32_t af[16][4];
#pragma unroll
        for (int s = 0; s < 16; s++) {
            af[s][0] = tf32c(__ldg(Wo1 + (8 * s + lr) * 128 + fA));
            af[s][1] = tf32c(__ldg(Wo1 + (8 * s + lr) * 128 + fA + 8));
            af[s][2] = tf32c(__ldg(Wo1 + (8 * s + 4 + lr) * 128 + fA));
            af[s][3] = tf32c(__ldg(Wo1 + (8 * s + 4 + lr) * 128 + fA + 8));
        }
        __syncthreads();
        float acc[8][4];
#pragma unroll
        for (int nt = 0; nt < 8; nt++) {
            acc[nt][0] = bo1_lo; acc[nt][1] = bo1_lo;
            acc[nt][2] = bo1_hi; acc[nt][3] = bo1_hi;
        }
#pragma unroll
        for (int nt = 0; nt < 8; nt++) {
            int gnt = ahalf * 8 + nt;
            const float2* bp = bbase + gnt * (NT_STRIDE / 2);
#pragma unroll
            for (int s = 0; s < 16; s++) {
                float2 bb = bp[s * (S_STRIDE / 2)];
                mma_tf32(acc[nt], af[s], __float_as_uint(bb.x), __float_as_uint(bb.y));
            }
        }
        __syncthreads();
#pragma unroll
        for (int nt = 0; nt < 8; nt++) {
            int gnt = ahalf * 8 + nt;
            float* base = sm + gnt * NT_STRIDE;
            int e0 = 2 * lr;
            base[p2_lo + e0 * 8]       = __uint_as_float(tf32c(sspf(acc[nt][0])));
            base[p2_lo + (e0 + 1) * 8] = __uint_as_float(tf32c(sspf(acc[nt][1])));
            base[p2_hi + e0 * 8]       = __uint_as_float(tf32c(sspf(acc[nt][2])));
            base[p2_hi + (e0 + 1) * 8] = __uint_as_float(tf32c(sspf(acc[nt][3])));
        }
#pragma unroll
        for (int s = 0; s < 16; s++) {
            af[s][0] = tf32c(__ldg(Wo2 + (8 * s + lr) * 128 + fA));
            af[s][1] = tf32c(__ldg(Wo2 + (8 * s + lr) * 128 + fA + 8));
            af[s][2] = tf32c(__ldg(Wo2 + (8 * s + 4 + lr) * 128 + fA));
            af[s][3] = tf32c(__ldg(Wo2 + (8 * s + 4 + lr) * 128 + fA + 8));
        }
        __syncthreads();
#pragma unroll
        for (int nt = 0; nt < 8; nt++) {
            acc[nt][0] = bo2_lo; acc[nt][1] = bo2_lo;
            acc[nt][2] = bo2_hi; acc[nt][3] = bo2_hi;
        }
#pragma unroll
        for (int nt = 0; nt < 8; nt++) {
            int gnt = ahalf * 8 + nt;
            const float2* bp = bbase + gnt * (NT_STRIDE / 2);
#pragma unroll
            for (int s = 0; s < 16; s++) {
                float2 bb = bp[s * (S_STRIDE / 2)];
                mma_tf32(acc[nt], af[s], __float_as_uint(bb.x), __float_as_uint(bb.y));
            }
        }
#pragma unroll
        for (int nt = 0; nt < 8; nt++) {
            int gnt = ahalf * 8 + nt;
            int row0 = r0 + gnt * 8 + 2 * lr;
            if (row0 < nRows) {
                out[(size_t)row0 * 128 + fA] = acc[nt][0];
                out[(size_t)row0 * 128 + fA + 8] = acc[nt][2];
            }
            if (row0 + 1 < nRows) {
                out[(size_t)(row0 + 1) * 128 + fA] = acc[nt][1];
                out[(size_t)(row0 + 1) * 128 + fA + 8] = acc[nt][3];
            }
        }
    }
}

// ---------- launch ----------
extern "C" void kernel_launch(void* const* d_in, const int* in_sizes, int n_in,
                              void* d_out, int out_size) {
    const float* x    = (const float*)d_in[0];
    const float* f_ij = (const float*)d_in[1];
    const float* rcut = (const float*)d_in[2];
    const float* W_in = (const float*)d_in[3];
    const float* b_in = (const float*)d_in[4];
    const float* Wf1  = (const float*)d_in[5];
    const float* bf1  = (const float*)d_in[6];
    const float* Wf2  = (const float*)d_in[7];
    const float* bf2  = (const float*)d_in[8];
    const float* Wo1  = (const float*)d_in[9];
    const float* bo1  = (const float*)d_in[10];
    const float* Wo2  = (const float*)d_in[11];
    const float* bo2  = (const float*)d_in[12];
    const int* idx_i  = (const int*)d_in[13];
    const int* idx_j  = (const int*)d_in[14];
    float* out = (float*)d_out;

    int nAtoms = in_sizes[0] / 128;
    int nPairs = in_sizes[2];

    const int SMEM_INOUT = SH_OUT * 4;       // 73728
    const int SMEM_EDGE  = EW_TOTAL * 4;     // 39168

    cudaFuncSetAttribute(k_in, cudaFuncAttributeMaxDynamicSharedMemorySize, SMEM_INOUT);
    cudaFuncSetAttribute(k_edge, cudaFuncAttributeMaxDynamicSharedMemorySize, SMEM_EDGE);
    cudaFuncSetAttribute(k_out, cudaFuncAttributeMaxDynamicSharedMemorySize, SMEM_INOUT);

    int rowTiles = (nAtoms + 127) / 128;
    k_in<<<rowTiles, 512, SMEM_INOUT>>>(x, W_in, b_in, nAtoms);
    k_edge<<<296, 256, SMEM_EDGE>>>(f_ij, rcut, idx_i, idx_j, Wf1, bf1, Wf2, bf2, nPairs);
    k_out<<<rowTiles, 512, SMEM_INOUT>>>(Wo1, bo1, Wo2, bo2, out, nAtoms);
}